// round 1
// baseline (speedup 1.0000x reference)
#include <cuda_runtime.h>
#include <math.h>

#define NB    4
#define NIM   5
#define NTRI  12288
#define PTOK  256
#define IMGC  1280
#define EMB   128
#define NHEADS 8

// ------------------- scratch (device globals, no allocs) -------------------
__device__ float g_vol [(size_t)NB*NIM*PTOK*256];          // [b][j][p][c]   5.2 MB
__device__ float g_kkvv[(size_t)NB*NTRI*NIM*256];          // [b][n][j][c]   252 MB
__device__ float g_tq  [(size_t)NB*NTRI*64];               // [b][n][c]      12.6 MB
__device__ float g_q   [(size_t)NB*NTRI*EMB];              // 25 MB
__device__ float g_qp  [(size_t)NB*NTRI*EMB];
__device__ float g_kp  [(size_t)NB*NTRI*NIM*EMB];          // 126 MB
__device__ float g_vp  [(size_t)NB*NTRI*NIM*EMB];          // 126 MB
__device__ float g_o   [(size_t)NB*NTRI*EMB];
__device__ float g_t   [(size_t)NB*NTRI*EMB];

// ------------------- positional encoding ----------------------------------
// pe[p, 2i] = sin(p * div_i), pe[p, 2i+1] = cos(p * div_i)
// div_i = expf(2i * (-ln(10000)/128))  -- fp32 like XLA.
// The angle pos*div is rounded to fp32 (matches JAX), then evaluated with
// fp64 sin/cos so accuracy is independent of fast-math flags.
__device__ __forceinline__ float pe_val(int pos, int c) {
    int i = c >> 1;
    float divf = expf((float)(2 * i) * (-0.07195578415606394f));
    float ang  = (float)pos * divf;
    return (float)((c & 1) ? cos((double)ang) : sin((double)ang));
}

// ------------------- generic tiled SGEMM -----------------------------------
// C[m, cb*128 + n] = sum_k A_row(m)[k] * W[n][k] + bias[n] (+ pe(m % pe_mod, n))
// A_row(m) = A + a_off + (m >> g_shift)*gstride + (m & mask)*lda
// BM=64, BK=16, 256 threads, microtile TM=4 x TN=BN/16.
// TRANSC: writes C[(b*BN + n)*trans_rows + nn] with m = b*trans_rows + nn.
template<int BN, bool TRANSC>
__global__ __launch_bounds__(256) void gemm_kernel(
    const float* __restrict__ A, long long a_off, int lda, int g_shift, long long gstride,
    const float* __restrict__ W0, const float* __restrict__ W1,
    const float* __restrict__ bias0, const float* __restrict__ bias1,
    float* __restrict__ C, int ldc, int K, int pe_mod, int trans_rows)
{
    constexpr int BM = 64;
    constexpr int BK = 16;
    constexpr int TM = 4;
    constexpr int TN = BN / 16;

    __shared__ float As[BK][BM];
    __shared__ float Ws[BK][BN];

    const int tid = threadIdx.x;
    const int tx  = tid & 15;
    const int ty  = tid >> 4;
    const int m0  = blockIdx.x * BM;
    const int cb  = blockIdx.y;
    const float* W    = cb ? W1 : W0;
    const float* bias = cb ? bias1 : bias0;
    const long long mmask = (1LL << g_shift) - 1;

    float acc[TM][TN];
#pragma unroll
    for (int i = 0; i < TM; i++)
#pragma unroll
        for (int j = 0; j < TN; j++) acc[i][j] = 0.f;

    // A-tile load mapping: 64 rows x 16 k  => 256 float4
    const int ar  = tid >> 2;
    const int akq = tid & 3;
    const long long am = m0 + ar;
    const float* aptr = A + a_off + (am >> g_shift) * gstride
                          + (am & mmask) * (long long)lda + akq * 4;

    for (int k0 = 0; k0 < K; k0 += BK) {
        float4 av = *(const float4*)(aptr + k0);
        As[akq*4+0][ar] = av.x;
        As[akq*4+1][ar] = av.y;
        As[akq*4+2][ar] = av.z;
        As[akq*4+3][ar] = av.w;

#pragma unroll
        for (int p = 0; p < BN / 64; p++) {
            int nrow = (tid >> 2) + p * 64;
            int wkq  = tid & 3;
            float4 wv = *(const float4*)(W + (long long)nrow * K + k0 + wkq * 4);
            Ws[wkq*4+0][nrow] = wv.x;
            Ws[wkq*4+1][nrow] = wv.y;
            Ws[wkq*4+2][nrow] = wv.z;
            Ws[wkq*4+3][nrow] = wv.w;
        }
        __syncthreads();

#pragma unroll
        for (int k = 0; k < BK; k++) {
            float4 a4 = *(const float4*)&As[k][ty * TM];
            float a[TM] = {a4.x, a4.y, a4.z, a4.w};
            float w[TN];
#pragma unroll
            for (int jv = 0; jv < TN / 4; jv++) {
                float4 w4 = *(const float4*)&Ws[k][tx * TN + jv * 4];
                w[jv*4+0] = w4.x; w[jv*4+1] = w4.y; w[jv*4+2] = w4.z; w[jv*4+3] = w4.w;
            }
#pragma unroll
            for (int i = 0; i < TM; i++)
#pragma unroll
                for (int j = 0; j < TN; j++)
                    acc[i][j] = fmaf(a[i], w[j], acc[i][j]);
        }
        __syncthreads();
    }

#pragma unroll
    for (int i = 0; i < TM; i++) {
        int m = m0 + ty * TM + i;
#pragma unroll
        for (int j = 0; j < TN; j++) {
            int n = tx * TN + j;
            float v = acc[i][j] + bias[n];
            if (pe_mod) v += pe_val(m % pe_mod, n);
            if (TRANSC) {
                int bb = m / trans_rows;
                int nn = m - bb * trans_rows;
                C[((long long)(bb * BN + n)) * trans_rows + nn] = v;
            } else {
                C[(long long)m * ldc + cb * 128 + n] = v;
            }
        }
    }
}

// ------------------- transpose triplane_feat -> tq -------------------------
// tq[b][n][c] = tf[b][c][n]    (c < 64, n < 12288)
__global__ __launch_bounds__(256) void transpose_tq_kernel(
    const float* __restrict__ tf)
{
    __shared__ float s[64][65];
    int b  = blockIdx.y;
    int n0 = blockIdx.x * 64;
    int tid = threadIdx.x;
    int t64 = tid & 63;
    int t4  = tid >> 6;
#pragma unroll
    for (int p = 0; p < 16; p++) {
        int c = t4 + p * 4;
        s[c][t64] = tf[((long long)(b * 64 + c)) * NTRI + n0 + t64];
    }
    __syncthreads();
#pragma unroll
    for (int p = 0; p < 16; p++) {
        int n = t4 + p * 4;
        g_tq[((long long)(b * NTRI + n0 + n)) * 64 + t64] = s[t64][n];
    }
}

// ------------------- projection + bilinear sampling ------------------------
// One block: (n-tile of 512, (j, c-chunk of 32), b). Caches the 16x16x32
// channel slice of g_vol in smem, then bilinearly samples 512 triplane points.
__global__ __launch_bounds__(128) void sample_kernel(const float* __restrict__ proj)
{
    constexpr int NTILE = 512;
    constexpr int CC = 32;
    __shared__ float s[256 * CC];   // [yx][c]  32 KB

    int b  = blockIdx.z;
    int jq = blockIdx.y;
    int j  = jq >> 3;
    int c0 = (jq & 7) * CC;
    int n0 = blockIdx.x * NTILE;
    int tid = threadIdx.x;

    // load the 16x16xCC slice
    const float* vol = g_vol + ((size_t)(b * NIM + j) * PTOK) * 256;
    {
        int yx2 = tid >> 3;     // 16 yx per pass
        int f2  = tid & 7;      // 8 float4 per yx (32 floats)
#pragma unroll
        for (int p = 0; p < 16; p++) {
            int yx = yx2 + p * 16;
            float4 v = *(const float4*)(vol + (size_t)yx * 256 + c0 + f2 * 4);
            *(float4*)&s[yx * CC + f2 * 4] = v;
        }
    }
    __syncthreads();

    // projection rows for (b, j)
    float P[3][4];
#pragma unroll
    for (int k = 0; k < 3; k++)
#pragma unroll
        for (int c = 0; c < 4; c++)
            P[k][c] = proj[((size_t)(b * NIM + j) * 4 + k) * 4 + c];

    const float SC = (float)(2.0 * (1.0 + 0.1 + 1e-05));   // 2.20002

    int c  = tid & (CC - 1);
    int nn = tid >> 5;          // 4 points in parallel (one per warp)

    for (int ni = nn; ni < NTILE; ni += 4) {
        int n = n0 + ni;
        int plane = n >> 12;
        int loc = n & 4095;
        float colf = (float)(loc & 63);
        float rowf = (float)(loc >> 6);
        float vx, vy, vz;
        if (plane == 0)      { vx = colf;  vy = 31.5f; vz = rowf; }
        else if (plane == 1) { vx = colf;  vy = rowf;  vz = 31.5f; }
        else                 { vx = 31.5f; vy = colf;  vz = rowf; }
        float cx = (vx / 63.0f - 0.5f) * SC;
        float cy = (vy / 63.0f - 0.5f) * SC;
        float cz = (vz / 63.0f - 0.5f) * SC;

        float ci0 = cx * P[0][0] + cy * P[0][1] + cz * P[0][2] + P[0][3];
        float ci1 = cx * P[1][0] + cy * P[1][1] + cz * P[1][2] + P[1][3];
        float ci2 = cx * P[2][0] + cy * P[2][1] + cz * P[2][2] + P[2][3];

        float x = ci0 / ci2 / 223.0f;
        float y = ci1 / ci2 / 223.0f;
        float gx = fminf(fmaxf((x - 0.5f) * 2.0f, -1.0f), 1.0f);
        float gy = fminf(fmaxf((y - 0.5f) * 2.0f, -1.0f), 1.0f);
        float ix = (gx + 1.0f) * 7.5f;   // (W-1)/2 = 7.5
        float iy = (gy + 1.0f) * 7.5f;
        float x0f = floorf(ix), y0f = floorf(iy);
        float wx = ix - x0f,    wy = iy - y0f;
        int x0 = min(max((int)x0f, 0), 15);
        int x1 = min(x0 + 1, 15);
        int y0 = min(max((int)y0f, 0), 15);
        int y1 = min(y0 + 1, 15);
        float w00 = (1.f - wy) * (1.f - wx);
        float w01 = (1.f - wy) * wx;
        float w10 = wy * (1.f - wx);
        float w11 = wy * wx;

        float r = w00 * s[(y0 * 16 + x0) * CC + c]
                + w01 * s[(y0 * 16 + x1) * CC + c]
                + w10 * s[(y1 * 16 + x0) * CC + c]
                + w11 * s[(y1 * 16 + x1) * CC + c];

        g_kkvv[(((size_t)(b * NTRI + n)) * NIM + j) * 256 + c0 + c] = r;
    }
}

// ------------------- tiny attention (5 keys per query) ---------------------
__global__ __launch_bounds__(256) void attn_kernel()
{
    int t = blockIdx.x * 256 + threadIdx.x;     // < NB*NTRI*NHEADS
    int h = t & 7;
    long long bn = t >> 3;

    const float* qr = g_qp + bn * EMB + h * 16;
    float q[16];
#pragma unroll
    for (int d = 0; d < 4; d++) {
        float4 v = *(const float4*)(qr + d * 4);
        q[d*4+0] = v.x; q[d*4+1] = v.y; q[d*4+2] = v.z; q[d*4+3] = v.w;
    }

    float sc[NIM];
    const float* kb = g_kp + bn * (NIM * EMB) + h * 16;
#pragma unroll
    for (int j = 0; j < NIM; j++) {
        float dot = 0.f;
#pragma unroll
        for (int d = 0; d < 4; d++) {
            float4 v = *(const float4*)(kb + j * EMB + d * 4);
            dot = fmaf(q[d*4+0], v.x, dot);
            dot = fmaf(q[d*4+1], v.y, dot);
            dot = fmaf(q[d*4+2], v.z, dot);
            dot = fmaf(q[d*4+3], v.w, dot);
        }
        sc[j] = dot * 0.25f;   // 1/sqrt(16)
    }

    float mx = sc[0];
#pragma unroll
    for (int j = 1; j < NIM; j++) mx = fmaxf(mx, sc[j]);
    float sum = 0.f;
#pragma unroll
    for (int j = 0; j < NIM; j++) { sc[j] = expf(sc[j] - mx); sum += sc[j]; }
    float inv = 1.f / sum;

    float o[16];
#pragma unroll
    for (int d = 0; d < 16; d++) o[d] = 0.f;
    const float* vb = g_vp + bn * (NIM * EMB) + h * 16;
#pragma unroll
    for (int j = 0; j < NIM; j++) {
        float w = sc[j] * inv;
#pragma unroll
        for (int d = 0; d < 4; d++) {
            float4 v = *(const float4*)(vb + j * EMB + d * 4);
            o[d*4+0] = fmaf(w, v.x, o[d*4+0]);
            o[d*4+1] = fmaf(w, v.y, o[d*4+1]);
            o[d*4+2] = fmaf(w, v.z, o[d*4+2]);
            o[d*4+3] = fmaf(w, v.w, o[d*4+3]);
        }
    }

    float* orow = g_o + bn * EMB + h * 16;
#pragma unroll
    for (int d = 0; d < 4; d++)
        *(float4*)(orow + d * 4) = make_float4(o[d*4+0], o[d*4+1], o[d*4+2], o[d*4+3]);
}

// ------------------- launch -------------------------------------------------
extern "C" void kernel_launch(void* const* d_in, const int* in_sizes, int n_in,
                              void* d_out, int out_size)
{
    const float* tf     = (const float*)d_in[0];
    const float* img    = (const float*)d_in[1];
    const float* proj   = (const float*)d_in[2];
    const float* k_w    = (const float*)d_in[4];
    const float* k_b    = (const float*)d_in[5];
    const float* q_w    = (const float*)d_in[6];
    const float* q_b    = (const float*)d_in[7];
    const float* v_w    = (const float*)d_in[8];
    const float* v_b    = (const float*)d_in[9];
    const float* in_w   = (const float*)d_in[10];
    const float* in_b   = (const float*)d_in[11];
    const float* out_w  = (const float*)d_in[12];
    const float* out_b  = (const float*)d_in[13];
    const float* conv_w = (const float*)d_in[14];
    const float* conv_b = (const float*)d_in[15];
    float* out = (float*)d_out;

    float *p_vol, *p_kkvv, *p_q, *p_qp, *p_kp, *p_vp, *p_o, *p_t, *p_tq;
    cudaGetSymbolAddress((void**)&p_vol,  g_vol);
    cudaGetSymbolAddress((void**)&p_kkvv, g_kkvv);
    cudaGetSymbolAddress((void**)&p_tq,   g_tq);
    cudaGetSymbolAddress((void**)&p_q,    g_q);
    cudaGetSymbolAddress((void**)&p_qp,   g_qp);
    cudaGetSymbolAddress((void**)&p_kp,   g_kp);
    cudaGetSymbolAddress((void**)&p_vp,   g_vp);
    cudaGetSymbolAddress((void**)&p_o,    g_o);
    cudaGetSymbolAddress((void**)&p_t,    g_t);

    // 1) KV GEMM: vol[b][j][p][0:128]=k-path, [128:256]=v-path (+pe over p)
    //    A rows grouped per (b,j): 256 rows, group stride 257*1280, skip CLS.
    gemm_kernel<128, false><<<dim3(5120 / 64, 2), 256>>>(
        img, 1280, 1280, 8, 257LL * 1280,
        k_w, v_w, k_b, v_b, p_vol, 256, IMGC, PTOK, 0);

    // 2) transpose triplane_feat -> tq
    transpose_tq_kernel<<<dim3(NTRI / 64, NB), 256>>>(tf);

    // 3) projection + bilinear sampling -> kkvv
    sample_kernel<<<dim3(NTRI / 512, NIM * 8, NB), 128>>>(proj);

    // 4) q = tq @ q_w^T + q_b + pe(n)
    gemm_kernel<128, false><<<dim3(NB * NTRI / 64, 1), 256>>>(
        p_tq, 0, 64, 40, 0, q_w, q_w, q_b, q_b, p_q, 128, 64, NTRI, 0);

    // 5) qp = q @ Wq^T + bq
    gemm_kernel<128, false><<<dim3(NB * NTRI / 64, 1), 256>>>(
        p_q, 0, 128, 40, 0, in_w, in_w, in_b, in_b, p_qp, 128, 128, 0, 0);

    // 6) kp = kk @ Wk^T + bk
    gemm_kernel<128, false><<<dim3(NB * NTRI * NIM / 64, 1), 256>>>(
        p_kkvv, 0, 256, 40, 0,
        in_w + 128 * 128, in_w + 128 * 128, in_b + 128, in_b + 128,
        p_kp, 128, 128, 0, 0);

    // 7) vp = vv @ Wv^T + bv
    gemm_kernel<128, false><<<dim3(NB * NTRI * NIM / 64, 1), 256>>>(
        p_kkvv, 128, 256, 40, 0,
        in_w + 256 * 128, in_w + 256 * 128, in_b + 256, in_b + 256,
        p_vp, 128, 128, 0, 0);

    // 8) attention over 5 images
    attn_kernel<<<NB * NTRI * NHEADS / 256, 256>>>();

    // 9) t = o @ out_w^T + out_b
    gemm_kernel<128, false><<<dim3(NB * NTRI / 64, 1), 256>>>(
        p_o, 0, 128, 40, 0, out_w, out_w, out_b, out_b, p_t, 128, 128, 0, 0);

    // 10) conv: out[b][oc][n] = sum_c t[b][n][c]*conv_w[oc][c] + conv_b[oc]
    gemm_kernel<64, true><<<dim3(NB * NTRI / 64, 1), 256>>>(
        p_t, 0, 128, 40, 0, conv_w, conv_w, conv_b, conv_b, out, 0, 128, 0, NTRI);
}

// round 2
// speedup vs baseline: 2.9671x; 2.9671x over previous
#include <cuda_runtime.h>
#include <math.h>

#define NB    4
#define NIM   5
#define NTRI  12288
#define PTOK  256
#define IMGC  1280
#define EMB   128

// ------------------- scratch (device globals, no allocs) -------------------
__device__ float g_pe_img[256 * 128];
__device__ float g_pe_tri[NTRI * 128];
__device__ float g_kwT[IMGC * 128];
__device__ float g_vwT[IMGC * 128];
__device__ float g_qwT[64 * 128];
__device__ float g_Wc [256 * IMGC];      // rows 0..127 = Wk@k_w, 128..255 = Wv@v_w
__device__ float g_Wqc[128 * 64];        // Wq@q_w
__device__ float g_bKV[256 * 256];       // [p][c] combined bias+pe for kv'
__device__ float g_bQ[128];
__device__ float g_bK[128];
__device__ float g_bV[128];
__device__ float g_peq[NTRI * 128];      // pe_tri@Wq^T + bQ
__device__ float g_vol[(size_t)NB * NIM * PTOK * 256];   // volKV' 5.2MB
__device__ float g_tq [(size_t)NB * NTRI * 64];
__device__ float g_qp [(size_t)NB * NTRI * EMB];
__device__ float g_o  [(size_t)NB * NTRI * EMB];
__device__ float g_t  [(size_t)NB * NTRI * EMB];

// ------------------- positional encoding ----------------------------------
__device__ __forceinline__ float pe_val(int pos, int c) {
    int i = c >> 1;
    float divf = expf((float)(2 * i) * (-0.07195578415606394f));
    float ang  = (float)pos * divf;
    return (float)((c & 1) ? cos((double)ang) : sin((double)ang));
}

__global__ __launch_bounds__(256) void pe_fill_kernel() {
    int idx = blockIdx.x * 256 + threadIdx.x;   // (256+12288)*128 total
    int r = idx >> 7, c = idx & 127;
    float v = pe_val(r < 256 ? r : r - 256, c);
    if (r < 256) g_pe_img[idx] = v;
    else         g_pe_tri[idx - 256 * 128] = v;
}

// ------------------- generic transpose (out[c][r] = in[r][c]) --------------
__global__ __launch_bounds__(256) void transpose_kernel(
    const float* __restrict__ in, float* __restrict__ out, int R, int C)
{
    __shared__ float s[32][33];
    int r0 = blockIdx.y * 32, c0 = blockIdx.x * 32;
    int tx = threadIdx.x & 31, ty = threadIdx.x >> 5;
#pragma unroll
    for (int i = 0; i < 4; i++) {
        int r = ty + i * 8;
        s[r][tx] = in[(long long)(r0 + r) * C + c0 + tx];
    }
    __syncthreads();
#pragma unroll
    for (int i = 0; i < 4; i++) {
        int cc = ty + i * 8;
        out[(long long)(c0 + cc) * R + r0 + tx] = s[tx][cc];
    }
}

// ------------------- bias combine: out[c] = W[c,:]·bin + badd[c] -----------
__global__ void bias_comb_kernel(const float* __restrict__ W,
                                 const float* __restrict__ bin,
                                 const float* __restrict__ badd,
                                 float* __restrict__ out)
{
    int c = threadIdx.x;   // 128 threads
    float s = badd[c];
    for (int d = 0; d < 128; d++) s = fmaf(W[c * 128 + d], bin[d], s);
    out[c] = s;
}

// ------------------- double-buffered SGEMM ----------------------------------
// C[m][gn] = sum_k A_row(m)[k] * W[gn][k]  (+bias[gn]) (+T[(m%t_mod)*ldt+gn])
// A_row(m) = A + a_off + (m>>g_shift)*gstride + (m & mask)*lda
// BM=128, BK=16, 256 threads, TM=8 x TN=BN/16, 2-stage smem.
template<int BN, bool TRANSC>
__global__ __launch_bounds__(256, 2) void gemm2_kernel(
    const float* __restrict__ A, long long a_off, int lda, int g_shift, long long gstride,
    const float* __restrict__ W, int ldw,
    const float* __restrict__ bias,
    const float* __restrict__ T, int t_mod, int ldt,
    float* __restrict__ C, int ldc, int K, int trans_rows)
{
    constexpr int BM = 128, BK = 16;
    constexpr int TM = 8, TN = BN / 16;
    constexpr int APAD = 132;           // 128 + 4 pad (keeps 16B alignment)
    constexpr int WPAD = BN + 4;

    __shared__ float As[2][BK][APAD];
    __shared__ float Ws[2][BK][WPAD];

    const int tid = threadIdx.x;
    const int tx = tid & 15, ty = tid >> 4;
    const int m0  = blockIdx.x * BM;
    const int nb0 = blockIdx.y * BN;

    // A load mapping: 2 float4 per thread (128 rows x 16 k)
    const int ar = tid >> 1;
    const int ak = (tid & 1) * 8;
    const long long am = m0 + ar;
    const long long mmask = (1LL << g_shift) - 1;
    const float* aptr = A + a_off + (am >> g_shift) * gstride
                          + (am & mmask) * (long long)lda + ak;

    // W load mapping
    const float* Wb = W + (long long)nb0 * ldw;
    int wr, wk;
    if (BN == 128) { wr = tid >> 1; wk = (tid & 1) * 8; }
    else           { wr = tid >> 2; wk = (tid & 3) * 4; }
    const float* wptr = Wb + (long long)wr * ldw + wk;

    float acc[TM][TN];
#pragma unroll
    for (int i = 0; i < TM; i++)
#pragma unroll
        for (int j = 0; j < TN; j++) acc[i][j] = 0.f;

    const int nk = K / BK;

    float4 a0, a1, w0, w1;
    a0 = *(const float4*)(aptr);
    a1 = *(const float4*)(aptr + 4);
    w0 = *(const float4*)(wptr);
    if (BN == 128) w1 = *(const float4*)(wptr + 4);

    // store tile 0
    {
        As[0][ak+0][ar] = a0.x; As[0][ak+1][ar] = a0.y;
        As[0][ak+2][ar] = a0.z; As[0][ak+3][ar] = a0.w;
        As[0][ak+4][ar] = a1.x; As[0][ak+5][ar] = a1.y;
        As[0][ak+6][ar] = a1.z; As[0][ak+7][ar] = a1.w;
        Ws[0][wk+0][wr] = w0.x; Ws[0][wk+1][wr] = w0.y;
        Ws[0][wk+2][wr] = w0.z; Ws[0][wk+3][wr] = w0.w;
        if (BN == 128) {
            Ws[0][wk+4][wr] = w1.x; Ws[0][wk+5][wr] = w1.y;
            Ws[0][wk+6][wr] = w1.z; Ws[0][wk+7][wr] = w1.w;
        }
    }
    __syncthreads();

    for (int it = 0; it < nk; ++it) {
        const int cur = it & 1;
        const bool more = (it + 1 < nk);
        if (more) {
            const float* ap = aptr + (it + 1) * BK;
            const float* wp = wptr + (it + 1) * BK;
            a0 = *(const float4*)(ap);
            a1 = *(const float4*)(ap + 4);
            w0 = *(const float4*)(wp);
            if (BN == 128) w1 = *(const float4*)(wp + 4);
        }

#pragma unroll
        for (int k = 0; k < BK; ++k) {
            float a[TM];
            {
                float4 t0 = *(const float4*)&As[cur][k][ty * TM];
                float4 t1 = *(const float4*)&As[cur][k][ty * TM + 4];
                a[0]=t0.x; a[1]=t0.y; a[2]=t0.z; a[3]=t0.w;
                a[4]=t1.x; a[5]=t1.y; a[6]=t1.z; a[7]=t1.w;
            }
            float w[TN];
            {
                float4 u0 = *(const float4*)&Ws[cur][k][tx * TN];
                w[0]=u0.x; w[1]=u0.y; w[2]=u0.z; w[3]=u0.w;
                if (TN == 8) {
                    float4 u1 = *(const float4*)&Ws[cur][k][tx * TN + 4];
                    w[4]=u1.x; w[5]=u1.y; w[6]=u1.z; w[7]=u1.w;
                }
            }
#pragma unroll
            for (int i = 0; i < TM; i++)
#pragma unroll
                for (int j = 0; j < TN; j++)
                    acc[i][j] = fmaf(a[i], w[j], acc[i][j]);
        }

        if (more) {
            const int nxt = (it + 1) & 1;
            As[nxt][ak+0][ar] = a0.x; As[nxt][ak+1][ar] = a0.y;
            As[nxt][ak+2][ar] = a0.z; As[nxt][ak+3][ar] = a0.w;
            As[nxt][ak+4][ar] = a1.x; As[nxt][ak+5][ar] = a1.y;
            As[nxt][ak+6][ar] = a1.z; As[nxt][ak+7][ar] = a1.w;
            Ws[nxt][wk+0][wr] = w0.x; Ws[nxt][wk+1][wr] = w0.y;
            Ws[nxt][wk+2][wr] = w0.z; Ws[nxt][wk+3][wr] = w0.w;
            if (BN == 128) {
                Ws[nxt][wk+4][wr] = w1.x; Ws[nxt][wk+5][wr] = w1.y;
                Ws[nxt][wk+6][wr] = w1.z; Ws[nxt][wk+7][wr] = w1.w;
            }
        }
        __syncthreads();
    }

#pragma unroll
    for (int i = 0; i < TM; i++) {
        const int m = m0 + ty * TM + i;
        int bb = 0, nn = 0;
        if (TRANSC) { bb = m / trans_rows; nn = m - bb * trans_rows; }
        const int mt = T ? (m % t_mod) : 0;
#pragma unroll
        for (int j = 0; j < TN; j++) {
            const int gn = nb0 + tx * TN + j;
            float v = acc[i][j];
            if (bias) v += bias[gn];
            if (T)    v += T[(long long)mt * ldt + gn];
            if (TRANSC) C[((long long)(bb * BN + gn)) * trans_rows + nn] = v;
            else        C[(long long)m * ldc + gn] = v;
        }
    }
}

// ------------------- transpose triplane_feat -> tq -------------------------
__global__ __launch_bounds__(256) void transpose_tq_kernel(const float* __restrict__ tf)
{
    __shared__ float s[64][65];
    int b  = blockIdx.y;
    int n0 = blockIdx.x * 64;
    int tid = threadIdx.x;
    int t64 = tid & 63;
    int t4  = tid >> 6;
#pragma unroll
    for (int p = 0; p < 16; p++) {
        int c = t4 + p * 4;
        s[c][t64] = tf[((long long)(b * 64 + c)) * NTRI + n0 + t64];
    }
    __syncthreads();
#pragma unroll
    for (int p = 0; p < 16; p++) {
        int n = t4 + p * 4;
        g_tq[((long long)(b * NTRI + n0 + n)) * 64 + t64] = s[t64][n];
    }
}

// ------------------- fused sample + attention -------------------------------
// One warp per triplane point. Gathers kp/vp directly from projected volume
// (volKV' in L2/L1), does per-head attention, writes o.
__global__ __launch_bounds__(256) void fused_attn_kernel(const float* __restrict__ proj)
{
    __shared__ float Ps[NIM][12];
    const int b = blockIdx.y;
    if (threadIdx.x < NIM * 12) {
        int j = threadIdx.x / 12, e = threadIdx.x - j * 12;
        Ps[j][e] = proj[((size_t)(b * NIM + j) * 4 + (e >> 2)) * 4 + (e & 3)];
    }
    __syncthreads();

    const int lane = threadIdx.x & 31;
    const int n = blockIdx.x * 8 + (threadIdx.x >> 5);

    const int plane = n >> 12;
    const int loc = n & 4095;
    const float colf = (float)(loc & 63);
    const float rowf = (float)(loc >> 6);
    float vx, vy, vz;
    if (plane == 0)      { vx = colf;  vy = 31.5f; vz = rowf; }
    else if (plane == 1) { vx = colf;  vy = rowf;  vz = 31.5f; }
    else                 { vx = 31.5f; vy = colf;  vz = rowf; }
    const float SC = (float)(2.0 * (1.0 + 0.1 + 1e-05));
    const float cx = (vx / 63.0f - 0.5f) * SC;
    const float cy = (vy / 63.0f - 0.5f) * SC;
    const float cz = (vz / 63.0f - 0.5f) * SC;

    const float4 q4 = *(const float4*)(g_qp + ((size_t)(b * NTRI + n)) * 128 + lane * 4);

    float4 vkeep[NIM];
    float score[NIM];

#pragma unroll
    for (int j = 0; j < NIM; ++j) {
        const float* P = Ps[j];
        float ci0 = cx * P[0] + cy * P[1] + cz * P[2]  + P[3];
        float ci1 = cx * P[4] + cy * P[5] + cz * P[6]  + P[7];
        float ci2 = cx * P[8] + cy * P[9] + cz * P[10] + P[11];
        float x = ci0 / ci2 / 223.0f;
        float y = ci1 / ci2 / 223.0f;
        float gx = fminf(fmaxf((x - 0.5f) * 2.0f, -1.0f), 1.0f);
        float gy = fminf(fmaxf((y - 0.5f) * 2.0f, -1.0f), 1.0f);
        float ix = (gx + 1.0f) * 7.5f;
        float iy = (gy + 1.0f) * 7.5f;
        float x0f = floorf(ix), y0f = floorf(iy);
        float wx = ix - x0f, wy = iy - y0f;
        int x0 = min(max((int)x0f, 0), 15);
        int x1 = min(x0 + 1, 15);
        int y0 = min(max((int)y0f, 0), 15);
        int y1 = min(y0 + 1, 15);
        float w00 = (1.f - wy) * (1.f - wx);
        float w01 = (1.f - wy) * wx;
        float w10 = wy * (1.f - wx);
        float w11 = wy * wx;

        const float* base = g_vol + (size_t)(b * NIM + j) * PTOK * 256;
        const int t00 = (y0 * 16 + x0) * 256, t01 = (y0 * 16 + x1) * 256;
        const int t10 = (y1 * 16 + x0) * 256, t11 = (y1 * 16 + x1) * 256;
        const int ck = lane * 4;

        float4 k00 = *(const float4*)(base + t00 + ck);
        float4 k01 = *(const float4*)(base + t01 + ck);
        float4 k10 = *(const float4*)(base + t10 + ck);
        float4 k11 = *(const float4*)(base + t11 + ck);
        float4 v00 = *(const float4*)(base + t00 + 128 + ck);
        float4 v01 = *(const float4*)(base + t01 + 128 + ck);
        float4 v10 = *(const float4*)(base + t10 + 128 + ck);
        float4 v11 = *(const float4*)(base + t11 + 128 + ck);

        float4 kk, vv;
        kk.x = w00*k00.x + w01*k01.x + w10*k10.x + w11*k11.x;
        kk.y = w00*k00.y + w01*k01.y + w10*k10.y + w11*k11.y;
        kk.z = w00*k00.z + w01*k01.z + w10*k10.z + w11*k11.z;
        kk.w = w00*k00.w + w01*k01.w + w10*k10.w + w11*k11.w;
        vv.x = w00*v00.x + w01*v01.x + w10*v10.x + w11*v11.x;
        vv.y = w00*v00.y + w01*v01.y + w10*v10.y + w11*v11.y;
        vv.z = w00*v00.z + w01*v01.z + w10*v10.z + w11*v11.z;
        vv.w = w00*v00.w + w01*v01.w + w10*v10.w + w11*v11.w;
        vkeep[j] = vv;

        float d = q4.x*kk.x + q4.y*kk.y + q4.z*kk.z + q4.w*kk.w;
        d += __shfl_xor_sync(0xffffffffu, d, 1);
        d += __shfl_xor_sync(0xffffffffu, d, 2);
        score[j] = d * 0.25f;
    }

    float mx = score[0];
#pragma unroll
    for (int j = 1; j < NIM; j++) mx = fmaxf(mx, score[j]);
    float sum = 0.f;
#pragma unroll
    for (int j = 0; j < NIM; j++) { score[j] = expf(score[j] - mx); sum += score[j]; }
    const float inv = 1.f / sum;

    float4 o = make_float4(0.f, 0.f, 0.f, 0.f);
#pragma unroll
    for (int j = 0; j < NIM; j++) {
        float w = score[j] * inv;
        o.x = fmaf(w, vkeep[j].x, o.x);
        o.y = fmaf(w, vkeep[j].y, o.y);
        o.z = fmaf(w, vkeep[j].z, o.z);
        o.w = fmaf(w, vkeep[j].w, o.w);
    }
    *(float4*)(g_o + ((size_t)(b * NTRI + n)) * 128 + lane * 4) = o;
}

// ------------------- launch -------------------------------------------------
extern "C" void kernel_launch(void* const* d_in, const int* in_sizes, int n_in,
                              void* d_out, int out_size)
{
    const float* tf     = (const float*)d_in[0];
    const float* img    = (const float*)d_in[1];
    const float* proj   = (const float*)d_in[2];
    const float* k_w    = (const float*)d_in[4];
    const float* k_b    = (const float*)d_in[5];
    const float* q_w    = (const float*)d_in[6];
    const float* q_b    = (const float*)d_in[7];
    const float* v_w    = (const float*)d_in[8];
    const float* v_b    = (const float*)d_in[9];
    const float* in_w   = (const float*)d_in[10];
    const float* in_b   = (const float*)d_in[11];
    const float* out_w  = (const float*)d_in[12];
    const float* out_b  = (const float*)d_in[13];
    const float* conv_w = (const float*)d_in[14];
    const float* conv_b = (const float*)d_in[15];
    float* out = (float*)d_out;

    float *p_pe_img, *p_pe_tri, *p_kwT, *p_vwT, *p_qwT, *p_Wc, *p_Wqc, *p_bKV;
    float *p_bQ, *p_bK, *p_bV, *p_peq, *p_vol, *p_tq, *p_qp, *p_o, *p_t;
    cudaGetSymbolAddress((void**)&p_pe_img, g_pe_img);
    cudaGetSymbolAddress((void**)&p_pe_tri, g_pe_tri);
    cudaGetSymbolAddress((void**)&p_kwT, g_kwT);
    cudaGetSymbolAddress((void**)&p_vwT, g_vwT);
    cudaGetSymbolAddress((void**)&p_qwT, g_qwT);
    cudaGetSymbolAddress((void**)&p_Wc,  g_Wc);
    cudaGetSymbolAddress((void**)&p_Wqc, g_Wqc);
    cudaGetSymbolAddress((void**)&p_bKV, g_bKV);
    cudaGetSymbolAddress((void**)&p_bQ,  g_bQ);
    cudaGetSymbolAddress((void**)&p_bK,  g_bK);
    cudaGetSymbolAddress((void**)&p_bV,  g_bV);
    cudaGetSymbolAddress((void**)&p_peq, g_peq);
    cudaGetSymbolAddress((void**)&p_vol, g_vol);
    cudaGetSymbolAddress((void**)&p_tq,  g_tq);
    cudaGetSymbolAddress((void**)&p_qp,  g_qp);
    cudaGetSymbolAddress((void**)&p_o,   g_o);
    cudaGetSymbolAddress((void**)&p_t,   g_t);

    const float* Wq = in_w;
    const float* Wk = in_w + 128 * 128;
    const float* Wv = in_w + 256 * 128;

    // --- precompute (tiny) ---
    pe_fill_kernel<<<(256 + NTRI) * 128 / 256, 256>>>();
    transpose_kernel<<<dim3(IMGC / 32, 4), 256>>>(k_w, p_kwT, 128, IMGC);
    transpose_kernel<<<dim3(IMGC / 32, 4), 256>>>(v_w, p_vwT, 128, IMGC);
    transpose_kernel<<<dim3(2, 4), 256>>>(q_w, p_qwT, 128, 64);
    bias_comb_kernel<<<1, 128>>>(Wq, q_b, in_b,       p_bQ);
    bias_comb_kernel<<<1, 128>>>(Wk, k_b, in_b + 128, p_bK);
    bias_comb_kernel<<<1, 128>>>(Wv, v_b, in_b + 256, p_bV);

    // Wc = [Wk@k_w ; Wv@v_w]  (2 x 128x1280)
    gemm2_kernel<128, false><<<dim3(1, 10), 256>>>(
        Wk, 0, 128, 40, 0, p_kwT, 128, nullptr, nullptr, 1, 0,
        p_Wc, IMGC, 128, 0);
    gemm2_kernel<128, false><<<dim3(1, 10), 256>>>(
        Wv, 0, 128, 40, 0, p_vwT, 128, nullptr, nullptr, 1, 0,
        p_Wc + 128 * IMGC, IMGC, 128, 0);
    // Wqc = Wq@q_w (128x64)
    gemm2_kernel<64, false><<<dim3(1, 1), 256>>>(
        Wq, 0, 128, 40, 0, p_qwT, 128, nullptr, nullptr, 1, 0,
        p_Wqc, 64, 128, 0);
    // bKV[p][0:128] = pe_img@Wk^T + bK ; [128:256] = pe_img@Wv^T + bV
    gemm2_kernel<128, false><<<dim3(2, 1), 256>>>(
        p_pe_img, 0, 128, 40, 0, Wk, 128, p_bK, nullptr, 1, 0,
        p_bKV, 256, 128, 0);
    gemm2_kernel<128, false><<<dim3(2, 1), 256>>>(
        p_pe_img, 0, 128, 40, 0, Wv, 128, p_bV, nullptr, 1, 0,
        p_bKV + 128, 256, 128, 0);
    // peq = pe_tri@Wq^T + bQ  (12288x128)
    gemm2_kernel<128, false><<<dim3(NTRI / 128, 1), 256>>>(
        p_pe_tri, 0, 128, 40, 0, Wq, 128, p_bQ, nullptr, 1, 0,
        p_peq, 128, 128, 0);

    // --- main pipeline ---
    // volKV' = img @ Wc^T + bKV[p]   (5120 x 1280 -> 256)
    gemm2_kernel<128, false><<<dim3(5120 / 128, 2), 256>>>(
        img, IMGC, IMGC, 8, 257LL * IMGC, p_Wc, IMGC, nullptr,
        p_bKV, 256, 256, p_vol, 256, IMGC, 0);

    transpose_tq_kernel<<<dim3(NTRI / 64, NB), 256>>>(tf);

    // qp = tq @ Wqc^T + peq[n]   (49152 x 64 -> 128)
    gemm2_kernel<128, false><<<dim3(NB * NTRI / 128, 1), 256>>>(
        p_tq, 0, 64, 40, 0, p_Wqc, 64, nullptr,
        p_peq, NTRI, 128, p_qp, 128, 64, 0);

    // fused sample + attention -> o
    fused_attn_kernel<<<dim3(NTRI / 8, NB), 256>>>(proj);

    // t = o @ out_w^T + out_b
    gemm2_kernel<128, false><<<dim3(NB * NTRI / 128, 1), 256>>>(
        p_o, 0, 128, 40, 0, out_w, 128, out_b, nullptr, 1, 0,
        p_t, 128, 128, 0);

    // out[b][oc][n] = t @ conv_w^T + conv_b (transposed write)
    gemm2_kernel<64, true><<<dim3(NB * NTRI / 128, 1), 256>>>(
        p_t, 0, 128, 40, 0, conv_w, 128, conv_b, nullptr, 1, 0,
        out, 0, 128, NTRI);
}

// round 3
// speedup vs baseline: 3.4619x; 1.1668x over previous
#include <cuda_runtime.h>
#include <math.h>

#define NB    4
#define NIM   5
#define NTRI  12288
#define PTOK  256
#define IMGC  1280
#define EMB   128

// ------------------- scratch (device globals, no allocs) -------------------
__device__ float g_pe_img[256 * 128];
__device__ float g_pe_tri[NTRI * 128];
__device__ float g_kwT[IMGC * 128];
__device__ float g_vwT[IMGC * 128];
__device__ float g_qwT[64 * 128];
__device__ float g_Wc [256 * IMGC];      // rows 0..127 = Wk@k_w, 128..255 = Wv@v_w
__device__ float g_Wqc[128 * 64];        // Wq@q_w
__device__ float g_Woc[64 * 128];        // conv_w@out_w
__device__ float g_bKV[256 * 256];       // [p][c] combined bias+pe for kv'
__device__ float g_bQ[128];
__device__ float g_bK[128];
__device__ float g_bV[128];
__device__ float g_boc[64];
__device__ float g_peq[NTRI * 128];      // pe_tri@Wq^T + bQ
__device__ float g_vol[(size_t)NB * NIM * PTOK * 256];   // volKV' 5.2MB
__device__ float g_tq [(size_t)NB * NTRI * 64];
__device__ float g_qp [(size_t)NB * NTRI * EMB];
__device__ float g_o  [(size_t)NB * NTRI * EMB];

// ------------------- fast fp32 positional encoding --------------------------
// Computes sin/cos(fl32(pos*div)) with FMA-exact Cody-Waite reduction and
// cephes minimax polynomials. ~1e-7 abs error, no fp64, fast-math safe.
__device__ __forceinline__ float pe_val(int pos, int c) {
    int i = c >> 1;
    float divf = expf((float)(2 * i) * (-0.07195578415606394f));
    float a = (float)pos * divf;                       // matches reference fl32
    float kf = rintf(a * 0.6366197723675814f);         // a * 2/pi ; kf in [0, 7823]
    float r = fmaf(-kf, 1.57079637050628662109375f, a);   // exact cancellation via FMA
    r = fmaf(-kf, -4.37113900018624283e-8f, r);
    float z = r * r;
    // sin(r), r in [-pi/4, pi/4]
    float p = fmaf(-1.9515295891e-4f, z, 8.3321608736e-3f);
    p = fmaf(p, z, -1.6666654611e-1f);
    float ps = fmaf(p * z, r, r);
    // cos(r)
    float q2 = fmaf(2.443315711809948e-5f, z, -1.388731625493765e-3f);
    q2 = fmaf(q2, z, 4.166664568298827e-2f);
    float pc = fmaf(q2, z * z, fmaf(-0.5f, z, 1.f));
    int qi = ((int)kf + (c & 1)) & 3;                  // +1 quadrant for cos
    float res = (qi & 1) ? pc : ps;
    return (qi & 2) ? -res : res;
}

__global__ __launch_bounds__(256) void pe_fill_kernel() {
    int idx = blockIdx.x * 256 + threadIdx.x;   // (256+12288)*128 total
    int r = idx >> 7, c = idx & 127;
    float v = pe_val(r < 256 ? r : r - 256, c);
    if (r < 256) g_pe_img[idx] = v;
    else         g_pe_tri[idx - 256 * 128] = v;
}

// ------------------- generic transpose (out[c][r] = in[r][c]) --------------
__global__ __launch_bounds__(256) void transpose_kernel(
    const float* __restrict__ in, float* __restrict__ out, int R, int C)
{
    __shared__ float s[32][33];
    int r0 = blockIdx.y * 32, c0 = blockIdx.x * 32;
    int tx = threadIdx.x & 31, ty = threadIdx.x >> 5;
#pragma unroll
    for (int i = 0; i < 4; i++) {
        int r = ty + i * 8;
        s[r][tx] = in[(long long)(r0 + r) * C + c0 + tx];
    }
    __syncthreads();
#pragma unroll
    for (int i = 0; i < 4; i++) {
        int cc = ty + i * 8;
        out[(long long)(c0 + cc) * R + r0 + tx] = s[tx][cc];
    }
}

// ------------------- bias combine: out[c] = W[c,:]·bin + badd[c] -----------
__global__ void bias_comb_kernel(const float* __restrict__ W,
                                 const float* __restrict__ bin,
                                 const float* __restrict__ badd,
                                 float* __restrict__ out, int n)
{
    int c = threadIdx.x;
    if (c >= n) return;
    float s = badd[c];
    for (int d = 0; d < 128; d++) s = fmaf(W[c * 128 + d], bin[d], s);
    out[c] = s;
}

// ------------------- Woc = conv_w @ out_w (64x128 @ 128x128) ----------------
__global__ __launch_bounds__(256) void woc_kernel(const float* __restrict__ conv_w,
                                                  const float* __restrict__ out_w)
{
    int idx = blockIdx.x * 256 + threadIdx.x;   // 64*128
    int oc = idx >> 7, c = idx & 127;
    float s = 0.f;
    for (int d = 0; d < 128; d++)
        s = fmaf(conv_w[oc * 128 + d], out_w[d * 128 + c], s);
    g_Woc[idx] = s;
}

// ------------------- double-buffered SGEMM ----------------------------------
// C[m][gn] = sum_k A_row(m)[k] * W[gn][k]  (+bias[gn]) (+T[(m%t_mod)*ldt+gn])
// A_row(m) = A + a_off + (m>>g_shift)*gstride + (m & mask)*lda
template<int BM, int BN, bool TRANSC>
__global__ __launch_bounds__(256, 2) void gemm2_kernel(
    const float* __restrict__ A, long long a_off, int lda, int g_shift, long long gstride,
    const float* __restrict__ W, int ldw,
    const float* __restrict__ bias,
    const float* __restrict__ T, int t_mod, int ldt,
    float* __restrict__ C, int ldc, int K, int trans_rows)
{
    constexpr int BK = 16;
    constexpr int TM = BM / 16;
    constexpr int TN = BN / 16;
    constexpr int APAD = BM + 4;
    constexpr int WPAD = BN + 4;

    __shared__ float As[2][BK][APAD];
    __shared__ float Ws[2][BK][WPAD];

    const int tid = threadIdx.x;
    const int tx = tid & 15, ty = tid >> 4;
    const int m0  = blockIdx.x * BM;
    const int nb0 = blockIdx.y * BN;

    // A load mapping
    int ar, ak;
    if (BM == 128) { ar = tid >> 1; ak = (tid & 1) * 8; }
    else           { ar = tid >> 2; ak = (tid & 3) * 4; }
    const long long am = m0 + ar;
    const long long mmask = (1LL << g_shift) - 1;
    const float* aptr = A + a_off + (am >> g_shift) * gstride
                          + (am & mmask) * (long long)lda + ak;

    // W load mapping
    const float* Wb = W + (long long)nb0 * ldw;
    int wr, wk;
    if (BN == 128) { wr = tid >> 1; wk = (tid & 1) * 8; }
    else           { wr = tid >> 2; wk = (tid & 3) * 4; }
    const float* wptr = Wb + (long long)wr * ldw + wk;

    float acc[TM][TN];
#pragma unroll
    for (int i = 0; i < TM; i++)
#pragma unroll
        for (int j = 0; j < TN; j++) acc[i][j] = 0.f;

    const int nk = K / BK;

    float4 a0, a1, w0, w1;
    a0 = *(const float4*)(aptr);
    if (BM == 128) a1 = *(const float4*)(aptr + 4);
    w0 = *(const float4*)(wptr);
    if (BN == 128) w1 = *(const float4*)(wptr + 4);

    {
        As[0][ak+0][ar] = a0.x; As[0][ak+1][ar] = a0.y;
        As[0][ak+2][ar] = a0.z; As[0][ak+3][ar] = a0.w;
        if (BM == 128) {
            As[0][ak+4][ar] = a1.x; As[0][ak+5][ar] = a1.y;
            As[0][ak+6][ar] = a1.z; As[0][ak+7][ar] = a1.w;
        }
        Ws[0][wk+0][wr] = w0.x; Ws[0][wk+1][wr] = w0.y;
        Ws[0][wk+2][wr] = w0.z; Ws[0][wk+3][wr] = w0.w;
        if (BN == 128) {
            Ws[0][wk+4][wr] = w1.x; Ws[0][wk+5][wr] = w1.y;
            Ws[0][wk+6][wr] = w1.z; Ws[0][wk+7][wr] = w1.w;
        }
    }
    __syncthreads();

    for (int it = 0; it < nk; ++it) {
        const int cur = it & 1;
        const bool more = (it + 1 < nk);
        if (more) {
            const float* ap = aptr + (it + 1) * BK;
            const float* wp = wptr + (it + 1) * BK;
            a0 = *(const float4*)(ap);
            if (BM == 128) a1 = *(const float4*)(ap + 4);
            w0 = *(const float4*)(wp);
            if (BN == 128) w1 = *(const float4*)(wp + 4);
        }

#pragma unroll
        for (int k = 0; k < BK; ++k) {
            float a[TM];
            {
                float4 t0 = *(const float4*)&As[cur][k][ty * TM];
                a[0]=t0.x; a[1]=t0.y; a[2]=t0.z; a[3]=t0.w;
                if (TM == 8) {
                    float4 t1 = *(const float4*)&As[cur][k][ty * TM + 4];
                    a[4]=t1.x; a[5]=t1.y; a[6]=t1.z; a[7]=t1.w;
                }
            }
            float w[TN];
            {
                float4 u0 = *(const float4*)&Ws[cur][k][tx * TN];
                w[0]=u0.x; w[1]=u0.y; w[2]=u0.z; w[3]=u0.w;
                if (TN == 8) {
                    float4 u1 = *(const float4*)&Ws[cur][k][tx * TN + 4];
                    w[4]=u1.x; w[5]=u1.y; w[6]=u1.z; w[7]=u1.w;
                }
            }
#pragma unroll
            for (int i = 0; i < TM; i++)
#pragma unroll
                for (int j = 0; j < TN; j++)
                    acc[i][j] = fmaf(a[i], w[j], acc[i][j]);
        }

        if (more) {
            const int nxt = (it + 1) & 1;
            As[nxt][ak+0][ar] = a0.x; As[nxt][ak+1][ar] = a0.y;
            As[nxt][ak+2][ar] = a0.z; As[nxt][ak+3][ar] = a0.w;
            if (BM == 128) {
                As[nxt][ak+4][ar] = a1.x; As[nxt][ak+5][ar] = a1.y;
                As[nxt][ak+6][ar] = a1.z; As[nxt][ak+7][ar] = a1.w;
            }
            Ws[nxt][wk+0][wr] = w0.x; Ws[nxt][wk+1][wr] = w0.y;
            Ws[nxt][wk+2][wr] = w0.z; Ws[nxt][wk+3][wr] = w0.w;
            if (BN == 128) {
                Ws[nxt][wk+4][wr] = w1.x; Ws[nxt][wk+5][wr] = w1.y;
                Ws[nxt][wk+6][wr] = w1.z; Ws[nxt][wk+7][wr] = w1.w;
            }
        }
        __syncthreads();
    }

#pragma unroll
    for (int i = 0; i < TM; i++) {
        const int m = m0 + ty * TM + i;
        int bb = 0, nn = 0;
        if (TRANSC) { bb = m / trans_rows; nn = m - bb * trans_rows; }
        const int mt = T ? (m % t_mod) : 0;
#pragma unroll
        for (int j = 0; j < TN; j++) {
            const int gn = nb0 + tx * TN + j;
            float v = acc[i][j];
            if (bias) v += bias[gn];
            if (T)    v += T[(long long)mt * ldt + gn];
            if (TRANSC) C[((long long)(bb * BN + gn)) * trans_rows + nn] = v;
            else        C[(long long)m * ldc + gn] = v;
        }
    }
}

// ------------------- transpose triplane_feat -> tq -------------------------
__global__ __launch_bounds__(256) void transpose_tq_kernel(const float* __restrict__ tf)
{
    __shared__ float s[64][65];
    int b  = blockIdx.y;
    int n0 = blockIdx.x * 64;
    int tid = threadIdx.x;
    int t64 = tid & 63;
    int t4  = tid >> 6;
#pragma unroll
    for (int p = 0; p < 16; p++) {
        int c = t4 + p * 4;
        s[c][t64] = tf[((long long)(b * 64 + c)) * NTRI + n0 + t64];
    }
    __syncthreads();
#pragma unroll
    for (int p = 0; p < 16; p++) {
        int n = t4 + p * 4;
        g_tq[((long long)(b * NTRI + n0 + n)) * 64 + t64] = s[t64][n];
    }
}

// ------------------- fused sample + attention -------------------------------
__global__ __launch_bounds__(256) void fused_attn_kernel(const float* __restrict__ proj)
{
    __shared__ float Ps[NIM][12];
    const int b = blockIdx.y;
    if (threadIdx.x < NIM * 12) {
        int j = threadIdx.x / 12, e = threadIdx.x - j * 12;
        Ps[j][e] = proj[((size_t)(b * NIM + j) * 4 + (e >> 2)) * 4 + (e & 3)];
    }
    __syncthreads();

    const int lane = threadIdx.x & 31;
    const int n = blockIdx.x * 8 + (threadIdx.x >> 5);

    const int plane = n >> 12;
    const int loc = n & 4095;
    const float colf = (float)(loc & 63);
    const float rowf = (float)(loc >> 6);
    float vx, vy, vz;
    if (plane == 0)      { vx = colf;  vy = 31.5f; vz = rowf; }
    else if (plane == 1) { vx = colf;  vy = rowf;  vz = 31.5f; }
    else                 { vx = 31.5f; vy = colf;  vz = rowf; }
    const float SC = (float)(2.0 * (1.0 + 0.1 + 1e-05));
    const float cx = (vx / 63.0f - 0.5f) * SC;
    const float cy = (vy / 63.0f - 0.5f) * SC;
    const float cz = (vz / 63.0f - 0.5f) * SC;

    const float4 q4 = *(const float4*)(g_qp + ((size_t)(b * NTRI + n)) * 128 + lane * 4);

    float4 vkeep[NIM];
    float score[NIM];

#pragma unroll
    for (int j = 0; j < NIM; ++j) {
        const float* P = Ps[j];
        float ci0 = cx * P[0] + cy * P[1] + cz * P[2]  + P[3];
        float ci1 = cx * P[4] + cy * P[5] + cz * P[6]  + P[7];
        float ci2 = cx * P[8] + cy * P[9] + cz * P[10] + P[11];
        float x = ci0 / ci2 / 223.0f;
        float y = ci1 / ci2 / 223.0f;
        float gx = fminf(fmaxf((x - 0.5f) * 2.0f, -1.0f), 1.0f);
        float gy = fminf(fmaxf((y - 0.5f) * 2.0f, -1.0f), 1.0f);
        float ix = (gx + 1.0f) * 7.5f;
        float iy = (gy + 1.0f) * 7.5f;
        float x0f = floorf(ix), y0f = floorf(iy);
        float wx = ix - x0f, wy = iy - y0f;
        int x0 = min(max((int)x0f, 0), 15);
        int x1 = min(x0 + 1, 15);
        int y0 = min(max((int)y0f, 0), 15);
        int y1 = min(y0 + 1, 15);
        float w00 = (1.f - wy) * (1.f - wx);
        float w01 = (1.f - wy) * wx;
        float w10 = wy * (1.f - wx);
        float w11 = wy * wx;

        const float* base = g_vol + (size_t)(b * NIM + j) * PTOK * 256;
        const int t00 = (y0 * 16 + x0) * 256, t01 = (y0 * 16 + x1) * 256;
        const int t10 = (y1 * 16 + x0) * 256, t11 = (y1 * 16 + x1) * 256;
        const int ck = lane * 4;

        float4 k00 = *(const float4*)(base + t00 + ck);
        float4 k01 = *(const float4*)(base + t01 + ck);
        float4 k10 = *(const float4*)(base + t10 + ck);
        float4 k11 = *(const float4*)(base + t11 + ck);
        float4 v00 = *(const float4*)(base + t00 + 128 + ck);
        float4 v01 = *(const float4*)(base + t01 + 128 + ck);
        float4 v10 = *(const float4*)(base + t10 + 128 + ck);
        float4 v11 = *(const float4*)(base + t11 + 128 + ck);

        float4 kk, vv;
        kk.x = w00*k00.x + w01*k01.x + w10*k10.x + w11*k11.x;
        kk.y = w00*k00.y + w01*k01.y + w10*k10.y + w11*k11.y;
        kk.z = w00*k00.z + w01*k01.z + w10*k10.z + w11*k11.z;
        kk.w = w00*k00.w + w01*k01.w + w10*k10.w + w11*k11.w;
        vv.x = w00*v00.x + w01*v01.x + w10*v10.x + w11*v11.x;
        vv.y = w00*v00.y + w01*v01.y + w10*v10.y + w11*v11.y;
        vv.z = w00*v00.z + w01*v01.z + w10*v10.z + w11*v11.z;
        vv.w = w00*v00.w + w01*v01.w + w10*v10.w + w11*v11.w;
        vkeep[j] = vv;

        float d = q4.x*kk.x + q4.y*kk.y + q4.z*kk.z + q4.w*kk.w;
        d += __shfl_xor_sync(0xffffffffu, d, 1);
        d += __shfl_xor_sync(0xffffffffu, d, 2);
        score[j] = d * 0.25f;
    }

    float mx = score[0];
#pragma unroll
    for (int j = 1; j < NIM; j++) mx = fmaxf(mx, score[j]);
    float sum = 0.f;
#pragma unroll
    for (int j = 0; j < NIM; j++) { score[j] = expf(score[j] - mx); sum += score[j]; }
    const float inv = 1.f / sum;

    float4 o = make_float4(0.f, 0.f, 0.f, 0.f);
#pragma unroll
    for (int j = 0; j < NIM; j++) {
        float w = score[j] * inv;
        o.x = fmaf(w, vkeep[j].x, o.x);
        o.y = fmaf(w, vkeep[j].y, o.y);
        o.z = fmaf(w, vkeep[j].z, o.z);
        o.w = fmaf(w, vkeep[j].w, o.w);
    }
    *(float4*)(g_o + ((size_t)(b * NTRI + n)) * 128 + lane * 4) = o;
}

// ------------------- launch -------------------------------------------------
extern "C" void kernel_launch(void* const* d_in, const int* in_sizes, int n_in,
                              void* d_out, int out_size)
{
    const float* tf     = (const float*)d_in[0];
    const float* img    = (const float*)d_in[1];
    const float* proj   = (const float*)d_in[2];
    const float* k_w    = (const float*)d_in[4];
    const float* k_b    = (const float*)d_in[5];
    const float* q_w    = (const float*)d_in[6];
    const float* q_b    = (const float*)d_in[7];
    const float* v_w    = (const float*)d_in[8];
    const float* v_b    = (const float*)d_in[9];
    const float* in_w   = (const float*)d_in[10];
    const float* in_b   = (const float*)d_in[11];
    const float* out_w  = (const float*)d_in[12];
    const float* out_b  = (const float*)d_in[13];
    const float* conv_w = (const float*)d_in[14];
    const float* conv_b = (const float*)d_in[15];
    float* out = (float*)d_out;

    float *p_pe_img, *p_pe_tri, *p_kwT, *p_vwT, *p_qwT, *p_Wc, *p_Wqc, *p_Woc, *p_bKV;
    float *p_bQ, *p_bK, *p_bV, *p_boc, *p_peq, *p_vol, *p_tq, *p_qp, *p_o;
    cudaGetSymbolAddress((void**)&p_pe_img, g_pe_img);
    cudaGetSymbolAddress((void**)&p_pe_tri, g_pe_tri);
    cudaGetSymbolAddress((void**)&p_kwT, g_kwT);
    cudaGetSymbolAddress((void**)&p_vwT, g_vwT);
    cudaGetSymbolAddress((void**)&p_qwT, g_qwT);
    cudaGetSymbolAddress((void**)&p_Wc,  g_Wc);
    cudaGetSymbolAddress((void**)&p_Wqc, g_Wqc);
    cudaGetSymbolAddress((void**)&p_Woc, g_Woc);
    cudaGetSymbolAddress((void**)&p_bKV, g_bKV);
    cudaGetSymbolAddress((void**)&p_bQ,  g_bQ);
    cudaGetSymbolAddress((void**)&p_bK,  g_bK);
    cudaGetSymbolAddress((void**)&p_bV,  g_bV);
    cudaGetSymbolAddress((void**)&p_boc, g_boc);
    cudaGetSymbolAddress((void**)&p_peq, g_peq);
    cudaGetSymbolAddress((void**)&p_vol, g_vol);
    cudaGetSymbolAddress((void**)&p_tq,  g_tq);
    cudaGetSymbolAddress((void**)&p_qp,  g_qp);
    cudaGetSymbolAddress((void**)&p_o,   g_o);

    const float* Wq = in_w;
    const float* Wk = in_w + 128 * 128;
    const float* Wv = in_w + 256 * 128;

    // --- precompute (tiny) ---
    pe_fill_kernel<<<(256 + NTRI) * 128 / 256, 256>>>();
    transpose_kernel<<<dim3(IMGC / 32, 4), 256>>>(k_w, p_kwT, 128, IMGC);
    transpose_kernel<<<dim3(IMGC / 32, 4), 256>>>(v_w, p_vwT, 128, IMGC);
    transpose_kernel<<<dim3(2, 4), 256>>>(q_w, p_qwT, 128, 64);
    bias_comb_kernel<<<1, 128>>>(Wq, q_b, in_b,       p_bQ, 128);
    bias_comb_kernel<<<1, 128>>>(Wk, k_b, in_b + 128, p_bK, 128);
    bias_comb_kernel<<<1, 128>>>(Wv, v_b, in_b + 256, p_bV, 128);
    bias_comb_kernel<<<1, 128>>>(conv_w, out_b, conv_b, p_boc, 64);
    woc_kernel<<<32, 256>>>(conv_w, out_w);

    // Wc = [Wk@k_w ; Wv@v_w]  (2 x 128x1280)
    gemm2_kernel<128, 128, false><<<dim3(1, 10), 256>>>(
        Wk, 0, 128, 40, 0, p_kwT, 128, nullptr, nullptr, 1, 0,
        p_Wc, IMGC, 128, 0);
    gemm2_kernel<128, 128, false><<<dim3(1, 10), 256>>>(
        Wv, 0, 128, 40, 0, p_vwT, 128, nullptr, nullptr, 1, 0,
        p_Wc + 128 * IMGC, IMGC, 128, 0);
    // Wqc = Wq@q_w (128x64)
    gemm2_kernel<128, 64, false><<<dim3(1, 1), 256>>>(
        Wq, 0, 128, 40, 0, p_qwT, 128, nullptr, nullptr, 1, 0,
        p_Wqc, 64, 128, 0);
    // bKV[p][0:128] = pe_img@Wk^T + bK ; [128:256] = pe_img@Wv^T + bV
    gemm2_kernel<128, 128, false><<<dim3(2, 1), 256>>>(
        p_pe_img, 0, 128, 40, 0, Wk, 128, p_bK, nullptr, 1, 0,
        p_bKV, 256, 128, 0);
    gemm2_kernel<128, 128, false><<<dim3(2, 1), 256>>>(
        p_pe_img, 0, 128, 40, 0, Wv, 128, p_bV, nullptr, 1, 0,
        p_bKV + 128, 256, 128, 0);
    // peq = pe_tri@Wq^T + bQ  (12288x128)
    gemm2_kernel<128, 128, false><<<dim3(NTRI / 128, 1), 256>>>(
        p_pe_tri, 0, 128, 40, 0, Wq, 128, p_bQ, nullptr, 1, 0,
        p_peq, 128, 128, 0);

    // --- main pipeline ---
    // volKV' = img @ Wc^T + bKV[p]   (5120 x 1280 -> 256), BM=64 for full chip
    gemm2_kernel<64, 128, false><<<dim3(5120 / 64, 2), 256>>>(
        img, IMGC, IMGC, 8, 257LL * IMGC, p_Wc, IMGC, nullptr,
        p_bKV, 256, 256, p_vol, 256, IMGC, 0);

    transpose_tq_kernel<<<dim3(NTRI / 64, NB), 256>>>(tf);

    // qp = tq @ Wqc^T + peq[n]   (49152 x 64 -> 128)
    gemm2_kernel<128, 128, false><<<dim3(NB * NTRI / 128, 1), 256>>>(
        p_tq, 0, 64, 40, 0, p_Wqc, 64, nullptr,
        p_peq, NTRI, 128, p_qp, 128, 64, 0);

    // fused sample + attention -> o
    fused_attn_kernel<<<dim3(NTRI / 8, NB), 256>>>(proj);

    // out[b][oc][n] = o @ Woc^T + boc (fused out-proj + conv, transposed write)
    gemm2_kernel<128, 64, true><<<dim3(NB * NTRI / 128, 1), 256>>>(
        p_o, 0, 128, 40, 0, p_Woc, 128, p_boc, nullptr, 1, 0,
        out, 0, 128, NTRI);
}

// round 4
// speedup vs baseline: 4.0998x; 1.1842x over previous
#include <cuda_runtime.h>
#include <math.h>

#define NB    4
#define NIM   5
#define NTRI  12288
#define PTOK  256
#define IMGC  1280
#define EMB   128

// ------------------- scratch (device globals, no allocs) -------------------
__device__ float g_pe_imgK[256 * 128];     // pe_img + k_b
__device__ float g_pe_imgV[256 * 128];     // pe_img + v_b
__device__ float g_pe_tri[NTRI * 128];     // pe_tri + q_b
__device__ float g_kwT[IMGC * 128];
__device__ float g_vwT[IMGC * 128];
__device__ float g_Wc [256 * IMGC];        // rows 0..127 = Wk@k_w, 128..255 = Wv@v_w
__device__ float g_Wqc[128 * 64];          // Wq@q_w
__device__ float g_Woc[64 * 128];          // conv_w@out_w
__device__ float g_bKV[256 * 256];         // [p][c] combined bias+pe for kv'
__device__ float g_boc[64];
__device__ float g_peq[NTRI * 128];        // (pe_tri+q_b)@Wq^T + in_b[0:128]
__device__ float g_vol[(size_t)NB * NIM * PTOK * 256];   // volKV' 5.2MB
__device__ float g_tq [(size_t)NB * NTRI * 64];
__device__ float g_qp [(size_t)NB * NTRI * EMB];
__device__ float g_o  [(size_t)NB * NTRI * EMB];

// ------------------- fast fp32 positional encoding --------------------------
__device__ __forceinline__ float pe_val(int pos, int c) {
    int i = c >> 1;
    float divf = expf((float)(2 * i) * (-0.07195578415606394f));
    float a = (float)pos * divf;
    float kf = rintf(a * 0.6366197723675814f);
    float r = fmaf(-kf, 1.57079637050628662109375f, a);
    r = fmaf(-kf, -4.37113900018624283e-8f, r);
    float z = r * r;
    float p = fmaf(-1.9515295891e-4f, z, 8.3321608736e-3f);
    p = fmaf(p, z, -1.6666654611e-1f);
    float ps = fmaf(p * z, r, r);
    float q2 = fmaf(2.443315711809948e-5f, z, -1.388731625493765e-3f);
    q2 = fmaf(q2, z, 4.166664568298827e-2f);
    float pc = fmaf(q2, z * z, fmaf(-0.5f, z, 1.f));
    int qi = ((int)kf + (c & 1)) & 3;
    float res = (qi & 1) ? pc : ps;
    return (qi & 2) ? -res : res;
}

__global__ __launch_bounds__(256) void pe_fill_kernel(
    const float* __restrict__ q_b, const float* __restrict__ k_b,
    const float* __restrict__ v_b)
{
    int idx = blockIdx.x * 256 + threadIdx.x;   // (256+12288)*128
    int r = idx >> 7, c = idx & 127;
    if (r < 256) {
        float v = pe_val(r, c);
        g_pe_imgK[idx] = v + k_b[c];
        g_pe_imgV[idx] = v + v_b[c];
    } else {
        g_pe_tri[idx - 256 * 128] = pe_val(r - 256, c) + q_b[c];
    }
}

// ------------------- merged transposes --------------------------------------
// blocks [0,160): k_w -> kwT ; [160,320): v_w -> vwT ; [320,1088): tf -> tq
__global__ __launch_bounds__(256) void transpose_all_kernel(
    const float* __restrict__ k_w, const float* __restrict__ v_w,
    const float* __restrict__ tf)
{
    __shared__ float s[64][65];
    int bid = blockIdx.x;
    int tid = threadIdx.x;
    if (bid < 320) {
        const float* in = (bid < 160) ? k_w : v_w;
        float* out = (bid < 160) ? g_kwT : g_vwT;
        int t = (bid < 160) ? bid : bid - 160;
        int c0 = (t % 40) * 32, r0 = (t / 40) * 32;   // R=128, C=1280
        int tx = tid & 31, ty = tid >> 5;
#pragma unroll
        for (int i = 0; i < 4; i++) {
            int r = ty + i * 8;
            s[r][tx] = in[(long long)(r0 + r) * IMGC + c0 + tx];
        }
        __syncthreads();
#pragma unroll
        for (int i = 0; i < 4; i++) {
            int cc = ty + i * 8;
            out[(long long)(c0 + cc) * 128 + r0 + tx] = s[tx][cc];
        }
    } else {
        int idx = bid - 320;               // 768 blocks
        int b = idx / 192, n0 = (idx % 192) * 64;
        int t64 = tid & 63, t4 = tid >> 6;
#pragma unroll
        for (int p = 0; p < 16; p++) {
            int c = t4 + p * 4;
            s[c][t64] = tf[((long long)(b * 64 + c)) * NTRI + n0 + t64];
        }
        __syncthreads();
#pragma unroll
        for (int p = 0; p < 16; p++) {
            int n = t4 + p * 4;
            g_tq[((long long)(b * NTRI + n0 + n)) * 64 + t64] = s[t64][n];
        }
    }
}

// ------------------- merged small precompute --------------------------------
// blocks [0,256): bKV row p ; [256,288): Wqc ; [288,320): Woc ; 320: boc
__global__ __launch_bounds__(256) void small_all_kernel(
    const float* __restrict__ in_w, const float* __restrict__ in_b,
    const float* __restrict__ q_w,
    const float* __restrict__ out_w, const float* __restrict__ out_b,
    const float* __restrict__ conv_w, const float* __restrict__ conv_b)
{
    const float* Wq = in_w;
    const float* Wk = in_w + 128 * 128;
    const float* Wv = in_w + 256 * 128;
    int bid = blockIdx.x, tid = threadIdx.x;
    if (bid < 256) {
        __shared__ float peK[128], peV[128];
        if (tid < 128) peK[tid] = g_pe_imgK[bid * 128 + tid];
        else           peV[tid - 128] = g_pe_imgV[bid * 128 + tid - 128];
        __syncthreads();
        float s;
        if (tid < 128) {
            s = in_b[128 + tid];
            const float* wr = Wk + tid * 128;
            for (int e = 0; e < 128; e++) s = fmaf(wr[e], peK[e], s);
        } else {
            int c = tid - 128;
            s = in_b[256 + c];
            const float* wr = Wv + c * 128;
            for (int e = 0; e < 128; e++) s = fmaf(wr[e], peV[e], s);
        }
        g_bKV[bid * 256 + tid] = s;
    } else if (bid < 288) {
        int idx = (bid - 256) * 256 + tid;   // 8192 = 128x64
        int i = idx >> 6, c = idx & 63;
        float s = 0.f;
        for (int e = 0; e < 128; e++)
            s = fmaf(Wq[i * 128 + e], q_w[e * 64 + c], s);
        g_Wqc[idx] = s;
    } else if (bid < 320) {
        int idx = (bid - 288) * 256 + tid;   // 8192 = 64x128
        int oc = idx >> 7, c = idx & 127;
        float s = 0.f;
        for (int d = 0; d < 128; d++)
            s = fmaf(conv_w[oc * 128 + d], out_w[d * 128 + c], s);
        g_Woc[idx] = s;
    } else {
        if (tid < 64) {
            float s = conv_b[tid];
            for (int d = 0; d < 128; d++)
                s = fmaf(conv_w[tid * 128 + d], out_b[d], s);
            g_boc[tid] = s;
        }
    }
}

// ------------------- FMA-lean SGEMM: BM=64, BN=64, 128 thr, TM=8 x TN=4 -----
// C[m][nb0+n] = sum_k A_row(m)[k] * W[nb0+n][k] (+bias) (+T[(m%t_mod)*ldt+gn])
// blockIdx.z==1 switches to (A2, W2, C2).
template<bool TRANSC>
__global__ __launch_bounds__(128, 4) void gemm3_kernel(
    const float* __restrict__ A, const float* __restrict__ A2,
    long long a_off, int lda, int g_shift, long long gstride,
    const float* __restrict__ W, const float* __restrict__ W2, int ldw,
    const float* __restrict__ bias,
    const float* __restrict__ T, int t_mod, int ldt,
    float* __restrict__ C, float* __restrict__ C2, int ldc, int K,
    int trans_rows)
{
    constexpr int BK = 16;
    if (blockIdx.z) { A = A2; W = W2; C = C2; }

    __shared__ float As[2][BK][68];
    __shared__ float Ws[2][BK][68];

    const int tid = threadIdx.x;
    const int tx = tid & 15, ty = tid >> 4;
    const int m0  = blockIdx.x * 64;
    const int nb0 = blockIdx.y * 64;

    const int ar = tid >> 1;
    const int ak = (tid & 1) * 8;
    const long long am = m0 + ar;
    const long long mmask = (1LL << g_shift) - 1;
    const float* aptr = A + a_off + (am >> g_shift) * gstride
                          + (am & mmask) * (long long)lda + ak;
    const float* wptr = W + (long long)(nb0 + ar) * ldw + ak;

    float acc[8][4];
#pragma unroll
    for (int i = 0; i < 8; i++)
#pragma unroll
        for (int j = 0; j < 4; j++) acc[i][j] = 0.f;

    const int nk = K / BK;
    float4 a0 = *(const float4*)(aptr);
    float4 a1 = *(const float4*)(aptr + 4);
    float4 w0 = *(const float4*)(wptr);
    float4 w1 = *(const float4*)(wptr + 4);

    As[0][ak+0][ar]=a0.x; As[0][ak+1][ar]=a0.y; As[0][ak+2][ar]=a0.z; As[0][ak+3][ar]=a0.w;
    As[0][ak+4][ar]=a1.x; As[0][ak+5][ar]=a1.y; As[0][ak+6][ar]=a1.z; As[0][ak+7][ar]=a1.w;
    Ws[0][ak+0][ar]=w0.x; Ws[0][ak+1][ar]=w0.y; Ws[0][ak+2][ar]=w0.z; Ws[0][ak+3][ar]=w0.w;
    Ws[0][ak+4][ar]=w1.x; Ws[0][ak+5][ar]=w1.y; Ws[0][ak+6][ar]=w1.z; Ws[0][ak+7][ar]=w1.w;
    __syncthreads();

    for (int it = 0; it < nk; ++it) {
        const int cur = it & 1;
        const bool more = (it + 1 < nk);
        if (more) {
            const float* ap = aptr + (it + 1) * BK;
            const float* wp = wptr + (it + 1) * BK;
            a0 = *(const float4*)(ap);
            a1 = *(const float4*)(ap + 4);
            w0 = *(const float4*)(wp);
            w1 = *(const float4*)(wp + 4);
        }
#pragma unroll
        for (int k = 0; k < BK; ++k) {
            float a[8];
            {
                float4 t0 = *(const float4*)&As[cur][k][ty * 8];
                float4 t1 = *(const float4*)&As[cur][k][ty * 8 + 4];
                a[0]=t0.x; a[1]=t0.y; a[2]=t0.z; a[3]=t0.w;
                a[4]=t1.x; a[5]=t1.y; a[6]=t1.z; a[7]=t1.w;
            }
            float4 u = *(const float4*)&Ws[cur][k][tx * 4];
            float w[4] = {u.x, u.y, u.z, u.w};
#pragma unroll
            for (int i = 0; i < 8; i++)
#pragma unroll
                for (int j = 0; j < 4; j++)
                    acc[i][j] = fmaf(a[i], w[j], acc[i][j]);
        }
        if (more) {
            const int nxt = (it + 1) & 1;
            As[nxt][ak+0][ar]=a0.x; As[nxt][ak+1][ar]=a0.y; As[nxt][ak+2][ar]=a0.z; As[nxt][ak+3][ar]=a0.w;
            As[nxt][ak+4][ar]=a1.x; As[nxt][ak+5][ar]=a1.y; As[nxt][ak+6][ar]=a1.z; As[nxt][ak+7][ar]=a1.w;
            Ws[nxt][ak+0][ar]=w0.x; Ws[nxt][ak+1][ar]=w0.y; Ws[nxt][ak+2][ar]=w0.z; Ws[nxt][ak+3][ar]=w0.w;
            Ws[nxt][ak+4][ar]=w1.x; Ws[nxt][ak+5][ar]=w1.y; Ws[nxt][ak+6][ar]=w1.z; Ws[nxt][ak+7][ar]=w1.w;
        }
        __syncthreads();
    }

    if (!TRANSC) {
#pragma unroll
        for (int i = 0; i < 8; i++) {
            const int m = m0 + ty * 8 + i;
            const int mt = T ? (m % t_mod) : 0;
            float4 v;
            float* vp = (float*)&v;
#pragma unroll
            for (int j = 0; j < 4; j++) {
                const int gn = nb0 + tx * 4 + j;
                float x = acc[i][j];
                if (bias) x += bias[gn];
                if (T)    x += T[(long long)mt * ldt + gn];
                vp[j] = x;
            }
            *(float4*)(C + (long long)m * ldc + nb0 + tx * 4) = v;
        }
    } else {
        __shared__ float Cs[64][65];
#pragma unroll
        for (int i = 0; i < 8; i++) {
            const int mm = ty * 8 + i;
#pragma unroll
            for (int j = 0; j < 4; j++) {
                const int gn = nb0 + tx * 4 + j;
                Cs[mm][tx * 4 + j] = acc[i][j] + (bias ? bias[gn] : 0.f);
            }
        }
        __syncthreads();
        const int gn_l = tid >> 1, half = tid & 1;
        const int bb = m0 / trans_rows;
        const int nn0 = m0 - bb * trans_rows;
        float* base = C + (long long)(bb * 64 + nb0 + gn_l) * trans_rows
                        + nn0 + half * 32;
#pragma unroll
        for (int s = 0; s < 8; s++) {
            float4 v;
            v.x = Cs[half * 32 + s * 4 + 0][gn_l];
            v.y = Cs[half * 32 + s * 4 + 1][gn_l];
            v.z = Cs[half * 32 + s * 4 + 2][gn_l];
            v.w = Cs[half * 32 + s * 4 + 3][gn_l];
            *(float4*)(base + s * 4) = v;
        }
    }
}

// ------------------- fused sample + attention -------------------------------
__global__ __launch_bounds__(256) void fused_attn_kernel(const float* __restrict__ proj)
{
    __shared__ float Ps[NIM][12];
    const int b = blockIdx.y;
    if (threadIdx.x < NIM * 12) {
        int j = threadIdx.x / 12, e = threadIdx.x - j * 12;
        Ps[j][e] = proj[((size_t)(b * NIM + j) * 4 + (e >> 2)) * 4 + (e & 3)];
    }
    __syncthreads();

    const int lane = threadIdx.x & 31;
    const int n = blockIdx.x * 8 + (threadIdx.x >> 5);

    const int plane = n >> 12;
    const int loc = n & 4095;
    const float colf = (float)(loc & 63);
    const float rowf = (float)(loc >> 6);
    float vx, vy, vz;
    if (plane == 0)      { vx = colf;  vy = 31.5f; vz = rowf; }
    else if (plane == 1) { vx = colf;  vy = rowf;  vz = 31.5f; }
    else                 { vx = 31.5f; vy = colf;  vz = rowf; }
    const float SC = (float)(2.0 * (1.0 + 0.1 + 1e-05));
    const float cx = (vx / 63.0f - 0.5f) * SC;
    const float cy = (vy / 63.0f - 0.5f) * SC;
    const float cz = (vz / 63.0f - 0.5f) * SC;

    const float4 q4 = *(const float4*)(g_qp + ((size_t)(b * NTRI + n)) * 128 + lane * 4);

    float4 vkeep[NIM];
    float score[NIM];

#pragma unroll
    for (int j = 0; j < NIM; ++j) {
        const float* P = Ps[j];
        float ci0 = cx * P[0] + cy * P[1] + cz * P[2]  + P[3];
        float ci1 = cx * P[4] + cy * P[5] + cz * P[6]  + P[7];
        float ci2 = cx * P[8] + cy * P[9] + cz * P[10] + P[11];
        float x = ci0 / ci2 / 223.0f;
        float y = ci1 / ci2 / 223.0f;
        float gx = fminf(fmaxf((x - 0.5f) * 2.0f, -1.0f), 1.0f);
        float gy = fminf(fmaxf((y - 0.5f) * 2.0f, -1.0f), 1.0f);
        float ix = (gx + 1.0f) * 7.5f;
        float iy = (gy + 1.0f) * 7.5f;
        float x0f = floorf(ix), y0f = floorf(iy);
        float wx = ix - x0f, wy = iy - y0f;
        int x0 = min(max((int)x0f, 0), 15);
        int x1 = min(x0 + 1, 15);
        int y0 = min(max((int)y0f, 0), 15);
        int y1 = min(y0 + 1, 15);
        float w00 = (1.f - wy) * (1.f - wx);
        float w01 = (1.f - wy) * wx;
        float w10 = wy * (1.f - wx);
        float w11 = wy * wx;

        const float* base = g_vol + (size_t)(b * NIM + j) * PTOK * 256;
        const int t00 = (y0 * 16 + x0) * 256, t01 = (y0 * 16 + x1) * 256;
        const int t10 = (y1 * 16 + x0) * 256, t11 = (y1 * 16 + x1) * 256;
        const int ck = lane * 4;

        float4 k00 = *(const float4*)(base + t00 + ck);
        float4 k01 = *(const float4*)(base + t01 + ck);
        float4 k10 = *(const float4*)(base + t10 + ck);
        float4 k11 = *(const float4*)(base + t11 + ck);
        float4 v00 = *(const float4*)(base + t00 + 128 + ck);
        float4 v01 = *(const float4*)(base + t01 + 128 + ck);
        float4 v10 = *(const float4*)(base + t10 + 128 + ck);
        float4 v11 = *(const float4*)(base + t11 + 128 + ck);

        float4 kk, vv;
        kk.x = w00*k00.x + w01*k01.x + w10*k10.x + w11*k11.x;
        kk.y = w00*k00.y + w01*k01.y + w10*k10.y + w11*k11.y;
        kk.z = w00*k00.z + w01*k01.z + w10*k10.z + w11*k11.z;
        kk.w = w00*k00.w + w01*k01.w + w10*k10.w + w11*k11.w;
        vv.x = w00*v00.x + w01*v01.x + w10*v10.x + w11*v11.x;
        vv.y = w00*v00.y + w01*v01.y + w10*v10.y + w11*v11.y;
        vv.z = w00*v00.z + w01*v01.z + w10*v10.z + w11*v11.z;
        vv.w = w00*v00.w + w01*v01.w + w10*v10.w + w11*v11.w;
        vkeep[j] = vv;

        float d = q4.x*kk.x + q4.y*kk.y + q4.z*kk.z + q4.w*kk.w;
        d += __shfl_xor_sync(0xffffffffu, d, 1);
        d += __shfl_xor_sync(0xffffffffu, d, 2);
        score[j] = d * 0.25f;
    }

    float mx = score[0];
#pragma unroll
    for (int j = 1; j < NIM; j++) mx = fmaxf(mx, score[j]);
    float sum = 0.f;
#pragma unroll
    for (int j = 0; j < NIM; j++) { score[j] = expf(score[j] - mx); sum += score[j]; }
    const float inv = 1.f / sum;

    float4 o = make_float4(0.f, 0.f, 0.f, 0.f);
#pragma unroll
    for (int j = 0; j < NIM; j++) {
        float w = score[j] * inv;
        o.x = fmaf(w, vkeep[j].x, o.x);
        o.y = fmaf(w, vkeep[j].y, o.y);
        o.z = fmaf(w, vkeep[j].z, o.z);
        o.w = fmaf(w, vkeep[j].w, o.w);
    }
    *(float4*)(g_o + ((size_t)(b * NTRI + n)) * 128 + lane * 4) = o;
}

// ------------------- launch -------------------------------------------------
extern "C" void kernel_launch(void* const* d_in, const int* in_sizes, int n_in,
                              void* d_out, int out_size)
{
    const float* tf     = (const float*)d_in[0];
    const float* img    = (const float*)d_in[1];
    const float* proj   = (const float*)d_in[2];
    const float* k_w    = (const float*)d_in[4];
    const float* k_b    = (const float*)d_in[5];
    const float* q_w    = (const float*)d_in[6];
    const float* q_b    = (const float*)d_in[7];
    const float* v_w    = (const float*)d_in[8];
    const float* v_b    = (const float*)d_in[9];
    const float* in_w   = (const float*)d_in[10];
    const float* in_b   = (const float*)d_in[11];
    const float* out_w  = (const float*)d_in[12];
    const float* out_b  = (const float*)d_in[13];
    const float* conv_w = (const float*)d_in[14];
    const float* conv_b = (const float*)d_in[15];
    float* out = (float*)d_out;

    float *p_kwT, *p_vwT, *p_Wc, *p_Wqc, *p_Woc, *p_bKV, *p_boc;
    float *p_peq, *p_pe_tri, *p_vol, *p_tq, *p_qp, *p_o;
    cudaGetSymbolAddress((void**)&p_kwT, g_kwT);
    cudaGetSymbolAddress((void**)&p_vwT, g_vwT);
    cudaGetSymbolAddress((void**)&p_Wc,  g_Wc);
    cudaGetSymbolAddress((void**)&p_Wqc, g_Wqc);
    cudaGetSymbolAddress((void**)&p_Woc, g_Woc);
    cudaGetSymbolAddress((void**)&p_bKV, g_bKV);
    cudaGetSymbolAddress((void**)&p_boc, g_boc);
    cudaGetSymbolAddress((void**)&p_peq, g_peq);
    cudaGetSymbolAddress((void**)&p_pe_tri, g_pe_tri);
    cudaGetSymbolAddress((void**)&p_vol, g_vol);
    cudaGetSymbolAddress((void**)&p_tq,  g_tq);
    cudaGetSymbolAddress((void**)&p_qp,  g_qp);
    cudaGetSymbolAddress((void**)&p_o,   g_o);

    const float* Wq = in_w;
    const float* Wk = in_w + 128 * 128;
    const float* Wv = in_w + 256 * 128;

    // 0) PE tables (+folded biases)
    pe_fill_kernel<<<(256 + NTRI) * 128 / 256, 256>>>(q_b, k_b, v_b);
    // 1) merged transposes: kwT, vwT, tq
    transpose_all_kernel<<<1088, 256>>>(k_w, v_w, tf);
    // 2) merged small precomputes: bKV, Wqc, Woc, boc
    small_all_kernel<<<321, 256>>>(in_w, in_b, q_w, out_w, out_b, conv_w, conv_b);
    // 3) Wc = [Wk@k_w ; Wv@v_w]  (z-merged, 80 CTAs)
    gemm3_kernel<false><<<dim3(2, 20, 2), 128>>>(
        Wk, Wv, 0, 128, 40, 0, p_kwT, p_vwT, 128,
        nullptr, nullptr, 1, 0, p_Wc, p_Wc + 128 * IMGC, IMGC, 128, 0);
    // 4) volKV' = img @ Wc^T + bKV[p]   (5120 x 1280 -> 256), 320 CTAs
    gemm3_kernel<false><<<dim3(80, 4, 1), 128>>>(
        img, img, 1280, IMGC, 8, 257LL * IMGC, p_Wc, p_Wc, IMGC,
        nullptr, p_bKV, 256, 256, p_vol, p_vol, 256, IMGC, 0);
    // 5) peq = (pe_tri+q_b) @ Wq^T + in_b[0:128]
    gemm3_kernel<false><<<dim3(192, 2, 1), 128>>>(
        p_pe_tri, p_pe_tri, 0, 128, 40, 0, Wq, Wq, 128,
        in_b, nullptr, 1, 0, p_peq, p_peq, 128, 128, 0);
    // 6) qp = tq @ Wqc^T + peq[n]
    gemm3_kernel<false><<<dim3(768, 2, 1), 128>>>(
        p_tq, p_tq, 0, 64, 40, 0, p_Wqc, p_Wqc, 64,
        nullptr, p_peq, NTRI, 128, p_qp, p_qp, 128, 64, 0);
    // 7) fused sample + attention -> o
    fused_attn_kernel<<<dim3(NTRI / 8, NB), 256>>>(proj);
    // 8) out[b][oc][n] = o @ Woc^T + boc (transposed, smem-staged store)
    gemm3_kernel<true><<<dim3(768, 1, 1), 128>>>(
        p_o, p_o, 0, 128, 40, 0, p_Woc, p_Woc, 128,
        p_boc, nullptr, 1, 0, out, out, 0, 128, NTRI);
}

// round 5
// speedup vs baseline: 6.6021x; 1.6104x over previous
#include <cuda_runtime.h>
#include <math.h>

#define NB    4
#define NIM   5
#define NTRI  12288
#define PTOK  256
#define IMGC  1280
#define EMB   128
#define NROWS (NB * NTRI)

// ------------------- scratch (device globals, no allocs) -------------------
__device__ float g_pe_imgK[256 * 128];             // pe_img + k_b
__device__ float g_pe_imgV[256 * 128];             // pe_img + v_b
__device__ float g_pe_triT[128 * NTRI];            // (pe_tri + q_b)^T  [c][n]
__device__ float g_WkT[128 * 128];                 // Wk^T
__device__ float g_WvT[128 * 128];                 // Wv^T
__device__ float g_WcT[IMGC * 256];                // [e][0:128]=Wk@k_w, [128:256]=Wv@v_w (K-major)
__device__ float g_WcatT[192 * 128];               // [k][i]: k<64 -> Wqc^T, else Wq^T
__device__ float g_WocT[128 * 64];                 // (conv_w@out_w)^T
__device__ float g_bKV[256 * 256];                 // [p][c] combined bias+pe for kv'
__device__ float g_boc[64];
__device__ float g_imgT[20LL * IMGC * 256];        // img tokens transposed  [g][k][p]  26MB
__device__ float g_vol[(size_t)NB * NIM * PTOK * 256];   // volKV' 5.2MB
__device__ float g_qp [(size_t)NROWS * EMB];       // 25MB
__device__ float g_oT [(size_t)EMB * NROWS];       // attention out, K-major  25MB

// ------------------- f32x2 helpers ------------------------------------------
__device__ __forceinline__ unsigned long long fma2(unsigned long long a,
                                                   unsigned long long b,
                                                   unsigned long long c) {
    unsigned long long d;
    asm("fma.rn.f32x2 %0, %1, %2, %3;" : "=l"(d) : "l"(a), "l"(b), "l"(c));
    return d;
}
__device__ __forceinline__ unsigned long long packdup(float x) {
    unsigned long long d;
    unsigned int u = __float_as_uint(x);
    asm("mov.b64 %0, {%1, %2};" : "=l"(d) : "r"(u), "r"(u));
    return d;
}
__device__ __forceinline__ void unpack2(unsigned long long v, float& lo, float& hi) {
    unsigned int a, b;
    asm("mov.b64 {%0, %1}, %2;" : "=r"(a), "=r"(b) : "l"(v));
    lo = __uint_as_float(a); hi = __uint_as_float(b);
}

// ------------------- fast fp32 positional encoding --------------------------
__device__ __forceinline__ float pe_val(int pos, int c) {
    int i = c >> 1;
    float divf = expf((float)(2 * i) * (-0.07195578415606394f));
    float a = (float)pos * divf;
    float kf = rintf(a * 0.6366197723675814f);
    float r = fmaf(-kf, 1.57079637050628662109375f, a);
    r = fmaf(-kf, -4.37113900018624283e-8f, r);
    float z = r * r;
    float p = fmaf(-1.9515295891e-4f, z, 8.3321608736e-3f);
    p = fmaf(p, z, -1.6666654611e-1f);
    float ps = fmaf(p * z, r, r);
    float q2 = fmaf(2.443315711809948e-5f, z, -1.388731625493765e-3f);
    q2 = fmaf(q2, z, 4.166664568298827e-2f);
    float pc = fmaf(q2, z * z, fmaf(-0.5f, z, 1.f));
    int qi = ((int)kf + (c & 1)) & 3;
    float res = (qi & 1) ? pc : ps;
    return (qi & 2) ? -res : res;
}

__global__ __launch_bounds__(256) void pe_fill_kernel(
    const float* __restrict__ q_b, const float* __restrict__ k_b,
    const float* __restrict__ v_b)
{
    int idx = blockIdx.x * 256 + threadIdx.x;
    if (idx < 256 * 128) {
        int r = idx >> 7, c = idx & 127;
        float v = pe_val(r, c);
        g_pe_imgK[idx] = v + k_b[c];
        g_pe_imgV[idx] = v + v_b[c];
    } else {
        int local = idx - 256 * 128;           // c * NTRI + n
        int c = local / NTRI, n = local - c * NTRI;
        g_pe_triT[local] = pe_val(n, c) + q_b[c];
    }
}

// ------------------- transposes: in_wT (Wk,Wv) + imgT ------------------------
__global__ __launch_bounds__(256) void transpose_all_kernel(
    const float* __restrict__ in_w, const float* __restrict__ img)
{
    __shared__ float s[32][33];
    int bid = blockIdx.x;
    int tid = threadIdx.x;
    int tx = tid & 31, ty = tid >> 5;
    if (bid < 32) {                      // Wk / Wv 128x128 transposes
        const float* src = in_w + (bid < 16 ? 128 * 128 : 256 * 128);
        float* dst = (bid < 16) ? g_WkT : g_WvT;
        int t = bid & 15;
        int r0 = (t >> 2) * 32, c0 = (t & 3) * 32;
#pragma unroll
        for (int i = 0; i < 4; i++)
            s[ty + i * 8][tx] = src[(r0 + ty + i * 8) * 128 + c0 + tx];
        __syncthreads();
#pragma unroll
        for (int i = 0; i < 4; i++)
            dst[(c0 + ty + i * 8) * 128 + r0 + tx] = s[tx][ty + i * 8];
    } else {                             // imgT: per (b,j) transpose 256x1280 -> 1280x256
        int t = bid - 32;                // 20 groups x 320 tiles
        int g = t / 320; t -= g * 320;
        int k0 = (t >> 3) * 32;          // 40 k-tiles
        int p0 = (t & 7) * 32;           // 8 p-tiles
        const float* src = img + (size_t)g * 257 * IMGC + IMGC;   // skip CLS
#pragma unroll
        for (int i = 0; i < 4; i++)
            s[ty + i * 8][tx] = src[(size_t)(p0 + ty + i * 8) * IMGC + k0 + tx];
        __syncthreads();
        float* dst = g_imgT + (size_t)g * IMGC * 256;
#pragma unroll
        for (int i = 0; i < 4; i++)
            dst[(size_t)(k0 + ty + i * 8) * 256 + p0 + tx] = s[tx][ty + i * 8];
    }
}

// ------------------- merged small precompute --------------------------------
// blocks [0,256): bKV row p ; [256,352): WcatT ; [352,384): WocT ; 384: boc
__global__ __launch_bounds__(256) void small_all_kernel(
    const float* __restrict__ in_w, const float* __restrict__ in_b,
    const float* __restrict__ q_w,
    const float* __restrict__ out_w, const float* __restrict__ out_b,
    const float* __restrict__ conv_w, const float* __restrict__ conv_b)
{
    const float* Wq = in_w;
    const float* Wk = in_w + 128 * 128;
    const float* Wv = in_w + 256 * 128;
    int bid = blockIdx.x, tid = threadIdx.x;
    if (bid < 256) {
        __shared__ float peK[128], peV[128];
        if (tid < 128) peK[tid] = g_pe_imgK[bid * 128 + tid];
        else           peV[tid - 128] = g_pe_imgV[bid * 128 + tid - 128];
        __syncthreads();
        float s;
        if (tid < 128) {
            s = in_b[128 + tid];
            const float* wr = Wk + tid * 128;
            for (int e = 0; e < 128; e++) s = fmaf(wr[e], peK[e], s);
        } else {
            int c = tid - 128;
            s = in_b[256 + c];
            const float* wr = Wv + c * 128;
            for (int e = 0; e < 128; e++) s = fmaf(wr[e], peV[e], s);
        }
        g_bKV[bid * 256 + tid] = s;
    } else if (bid < 352) {
        int idx = (bid - 256) * 256 + tid;   // 192*128, k*128+i
        int k = idx >> 7, i = idx & 127;
        float s;
        if (k < 64) {
            s = 0.f;
            for (int e = 0; e < 128; e++)
                s = fmaf(Wq[i * 128 + e], q_w[e * 64 + k], s);
        } else {
            s = Wq[i * 128 + (k - 64)];
        }
        g_WcatT[idx] = s;
    } else if (bid < 384) {
        int idx = (bid - 352) * 256 + tid;   // 128*64, c*64+oc
        int c = idx >> 6, oc = idx & 63;
        float s = 0.f;
        for (int d = 0; d < 128; d++)
            s = fmaf(conv_w[oc * 128 + d], out_w[d * 128 + c], s);
        g_WocT[idx] = s;
    } else if (tid < 64) {
        float s = conv_b[tid];
        for (int d = 0; d < 128; d++)
            s = fmaf(conv_w[tid * 128 + d], out_b[d], s);
        g_boc[tid] = s;
    }
}

// ------------------- FFMA2 SGEMM: K-major operands ---------------------------
// C[m][n0+n] = sum_k A[k][m] * W[k][n0+n]  (+bias) (+T[(m%t_mod)*ldt+n])
// A column addressing: base = A1 + (m/gdiv)*gstride + (m%gdiv); k-stride lda1.
// Concat: rows k>=kSplit come from A2 + (m%mod2) + (k-kSplit)*lda2.
struct GCfg {
    const float* A1; long long gdiv; long long gstride; int lda1;
    const float* A2; int lda2; long long mod2; int kSplit;
    const float* W; int ldw;
    const float* bias; const float* T; int t_mod; int ldt;
    float* C; int ldc; int K; int ny; int trans_rows;
};

template<bool TRANSC>
__global__ __launch_bounds__(128, 4) void gemm_f2_kernel(GCfg c0, GCfg c1, int count0)
{
    const bool first = (blockIdx.x < (unsigned)count0);
    GCfg cfg = first ? c0 : c1;
    const int local = first ? blockIdx.x : blockIdx.x - count0;

    __shared__ __align__(16) float As[2][16][68];
    __shared__ __align__(16) float Ws[2][16][68];

    const int tid = threadIdx.x;
    const int tx = tid & 15, ty = tid >> 4;
    const int m0 = (local / cfg.ny) * 64;
    const int n0 = (local % cfg.ny) * 64;

    const int kr = tid >> 3;
    const int cq = (tid & 7) * 8;
    const long long cm = m0 + cq;
    const float* base1 = cfg.A1 + (cm / cfg.gdiv) * cfg.gstride + (cm % cfg.gdiv);
    const float* base2 = cfg.A2 ? (cfg.A2 + (cm % cfg.mod2)) : nullptr;
    const float* wbase = cfg.W + n0 + cq;
    const bool concat = (cfg.A2 != nullptr);

    unsigned long long acc[4][4];
#pragma unroll
    for (int i = 0; i < 4; i++)
#pragma unroll
        for (int j = 0; j < 4; j++) acc[i][j] = 0ULL;

    const int nk = cfg.K / 16;

    float4 a0, a1, w0, w1;
    {
        int kk = kr;
        const float* p = (concat && kk >= cfg.kSplit)
            ? base2 + (size_t)(kk - cfg.kSplit) * cfg.lda2
            : base1 + (size_t)kk * cfg.lda1;
        a0 = *(const float4*)p; a1 = *(const float4*)(p + 4);
        const float* q = wbase + (size_t)kk * cfg.ldw;
        w0 = *(const float4*)q; w1 = *(const float4*)(q + 4);
    }
    *(float4*)&As[0][kr][cq]     = a0;
    *(float4*)&As[0][kr][cq + 4] = a1;
    *(float4*)&Ws[0][kr][cq]     = w0;
    *(float4*)&Ws[0][kr][cq + 4] = w1;
    __syncthreads();

    for (int it = 0; it < nk; ++it) {
        const int cur = it & 1;
        const bool more = (it + 1 < nk);
        if (more) {
            int kk = (it + 1) * 16 + kr;
            const float* p = (concat && kk >= cfg.kSplit)
                ? base2 + (size_t)(kk - cfg.kSplit) * cfg.lda2
                : base1 + (size_t)kk * cfg.lda1;
            a0 = *(const float4*)p; a1 = *(const float4*)(p + 4);
            const float* q = wbase + (size_t)kk * cfg.ldw;
            w0 = *(const float4*)q; w1 = *(const float4*)(q + 4);
        }
#pragma unroll
        for (int k = 0; k < 16; ++k) {
            const float* arow = &As[cur][k][ty * 8];
            ulonglong2 p0 = *(const ulonglong2*)arow;
            ulonglong2 p1 = *(const ulonglong2*)(arow + 4);
            unsigned long long a2[4] = {p0.x, p0.y, p1.x, p1.y};
            float4 u = *(const float4*)&Ws[cur][k][tx * 4];
            unsigned long long w2[4] = {packdup(u.x), packdup(u.y),
                                        packdup(u.z), packdup(u.w)};
#pragma unroll
            for (int i = 0; i < 4; i++)
#pragma unroll
                for (int j = 0; j < 4; j++)
                    acc[i][j] = fma2(a2[i], w2[j], acc[i][j]);
        }
        if (more) {
            const int nxt = (it + 1) & 1;
            *(float4*)&As[nxt][kr][cq]     = a0;
            *(float4*)&As[nxt][kr][cq + 4] = a1;
            *(float4*)&Ws[nxt][kr][cq]     = w0;
            *(float4*)&Ws[nxt][kr][cq + 4] = w1;
        }
        __syncthreads();
    }

    if (!TRANSC) {
#pragma unroll
        for (int i = 0; i < 4; i++) {
            float clo[4], chi[4];
#pragma unroll
            for (int j = 0; j < 4; j++) unpack2(acc[i][j], clo[j], chi[j]);
#pragma unroll
            for (int h = 0; h < 2; h++) {
                const int m = m0 + ty * 8 + i * 2 + h;
                const int mt = cfg.T ? (m % cfg.t_mod) : 0;
                float4 v;
                float* vp = (float*)&v;
#pragma unroll
                for (int j = 0; j < 4; j++) {
                    const int gn = n0 + tx * 4 + j;
                    float x = h ? chi[j] : clo[j];
                    if (cfg.bias) x += cfg.bias[gn];
                    if (cfg.T)    x += cfg.T[(size_t)mt * cfg.ldt + gn];
                    vp[j] = x;
                }
                *(float4*)(cfg.C + (size_t)m * cfg.ldc + n0 + tx * 4) = v;
            }
        }
    } else {
        __shared__ float Cs[64][65];
#pragma unroll
        for (int i = 0; i < 4; i++) {
            float clo[4], chi[4];
#pragma unroll
            for (int j = 0; j < 4; j++) unpack2(acc[i][j], clo[j], chi[j]);
#pragma unroll
            for (int j = 0; j < 4; j++) {
                const int gn = n0 + tx * 4 + j;
                const float bb = cfg.bias ? cfg.bias[gn] : 0.f;
                Cs[ty * 8 + i * 2 + 0][tx * 4 + j] = clo[j] + bb;
                Cs[ty * 8 + i * 2 + 1][tx * 4 + j] = chi[j] + bb;
            }
        }
        __syncthreads();
        const int gn_l = tid >> 1, half = tid & 1;
        const int bb = m0 / cfg.trans_rows;
        const int nn0 = m0 - bb * cfg.trans_rows;
        float* base = cfg.C + (size_t)(bb * 64 + n0 + gn_l) * cfg.trans_rows
                        + nn0 + half * 32;
#pragma unroll
        for (int s = 0; s < 8; s++) {
            float4 v;
            v.x = Cs[half * 32 + s * 4 + 0][gn_l];
            v.y = Cs[half * 32 + s * 4 + 1][gn_l];
            v.z = Cs[half * 32 + s * 4 + 2][gn_l];
            v.w = Cs[half * 32 + s * 4 + 3][gn_l];
            *(float4*)(base + s * 4) = v;
        }
    }
}

// ------------------- fused sample + attention (writes oT) --------------------
__global__ __launch_bounds__(256) void fused_attn_kernel(const float* __restrict__ proj)
{
    __shared__ float Ps[NIM][12];
    __shared__ float o_s[8][132];
    const int b = blockIdx.y;
    if (threadIdx.x < NIM * 12) {
        int j = threadIdx.x / 12, e = threadIdx.x - j * 12;
        Ps[j][e] = proj[((size_t)(b * NIM + j) * 4 + (e >> 2)) * 4 + (e & 3)];
    }
    __syncthreads();

    const int lane = threadIdx.x & 31;
    const int wp = threadIdx.x >> 5;
    const int n = blockIdx.x * 8 + wp;

    const int plane = n >> 12;
    const int loc = n & 4095;
    const float colf = (float)(loc & 63);
    const float rowf = (float)(loc >> 6);
    float vx, vy, vz;
    if (plane == 0)      { vx = colf;  vy = 31.5f; vz = rowf; }
    else if (plane == 1) { vx = colf;  vy = rowf;  vz = 31.5f; }
    else                 { vx = 31.5f; vy = colf;  vz = rowf; }
    const float SC = (float)(2.0 * (1.0 + 0.1 + 1e-05));
    const float cx = (vx / 63.0f - 0.5f) * SC;
    const float cy = (vy / 63.0f - 0.5f) * SC;
    const float cz = (vz / 63.0f - 0.5f) * SC;

    const float4 q4 = *(const float4*)(g_qp + ((size_t)(b * NTRI + n)) * 128 + lane * 4);

    float4 vkeep[NIM];
    float score[NIM];

#pragma unroll
    for (int j = 0; j < NIM; ++j) {
        const float* P = Ps[j];
        float ci0 = cx * P[0] + cy * P[1] + cz * P[2]  + P[3];
        float ci1 = cx * P[4] + cy * P[5] + cz * P[6]  + P[7];
        float ci2 = cx * P[8] + cy * P[9] + cz * P[10] + P[11];
        float x = ci0 / ci2 / 223.0f;
        float y = ci1 / ci2 / 223.0f;
        float gx = fminf(fmaxf((x - 0.5f) * 2.0f, -1.0f), 1.0f);
        float gy = fminf(fmaxf((y - 0.5f) * 2.0f, -1.0f), 1.0f);
        float ix = (gx + 1.0f) * 7.5f;
        float iy = (gy + 1.0f) * 7.5f;
        float x0f = floorf(ix), y0f = floorf(iy);
        float wx = ix - x0f, wy = iy - y0f;
        int x0 = min(max((int)x0f, 0), 15);
        int x1 = min(x0 + 1, 15);
        int y0 = min(max((int)y0f, 0), 15);
        int y1 = min(y0 + 1, 15);
        float w00 = (1.f - wy) * (1.f - wx);
        float w01 = (1.f - wy) * wx;
        float w10 = wy * (1.f - wx);
        float w11 = wy * wx;

        const float* base = g_vol + (size_t)(b * NIM + j) * PTOK * 256;
        const int t00 = (y0 * 16 + x0) * 256, t01 = (y0 * 16 + x1) * 256;
        const int t10 = (y1 * 16 + x0) * 256, t11 = (y1 * 16 + x1) * 256;
        const int ck = lane * 4;

        float4 k00 = *(const float4*)(base + t00 + ck);
        float4 k01 = *(const float4*)(base + t01 + ck);
        float4 k10 = *(const float4*)(base + t10 + ck);
        float4 k11 = *(const float4*)(base + t11 + ck);

        // per-tap dots, then scalar blend
        float d00 = q4.x*k00.x; d00 = fmaf(q4.y,k00.y,d00); d00 = fmaf(q4.z,k00.z,d00); d00 = fmaf(q4.w,k00.w,d00);
        float d01 = q4.x*k01.x; d01 = fmaf(q4.y,k01.y,d01); d01 = fmaf(q4.z,k01.z,d01); d01 = fmaf(q4.w,k01.w,d01);
        float d10 = q4.x*k10.x; d10 = fmaf(q4.y,k10.y,d10); d10 = fmaf(q4.z,k10.z,d10); d10 = fmaf(q4.w,k10.w,d10);
        float d11 = q4.x*k11.x; d11 = fmaf(q4.y,k11.y,d11); d11 = fmaf(q4.z,k11.z,d11); d11 = fmaf(q4.w,k11.w,d11);
        float d = w00*d00; d = fmaf(w01,d01,d); d = fmaf(w10,d10,d); d = fmaf(w11,d11,d);
        d += __shfl_xor_sync(0xffffffffu, d, 1);
        d += __shfl_xor_sync(0xffffffffu, d, 2);
        score[j] = d * 0.25f;

        float4 v00 = *(const float4*)(base + t00 + 128 + ck);
        float4 v01 = *(const float4*)(base + t01 + 128 + ck);
        float4 v10 = *(const float4*)(base + t10 + 128 + ck);
        float4 v11 = *(const float4*)(base + t11 + 128 + ck);
        float4 vv;
        vv.x = w00*v00.x; vv.x = fmaf(w01,v01.x,vv.x); vv.x = fmaf(w10,v10.x,vv.x); vv.x = fmaf(w11,v11.x,vv.x);
        vv.y = w00*v00.y; vv.y = fmaf(w01,v01.y,vv.y); vv.y = fmaf(w10,v10.y,vv.y); vv.y = fmaf(w11,v11.y,vv.y);
        vv.z = w00*v00.z; vv.z = fmaf(w01,v01.z,vv.z); vv.z = fmaf(w10,v10.z,vv.z); vv.z = fmaf(w11,v11.z,vv.z);
        vv.w = w00*v00.w; vv.w = fmaf(w01,v01.w,vv.w); vv.w = fmaf(w10,v10.w,vv.w); vv.w = fmaf(w11,v11.w,vv.w);
        vkeep[j] = vv;
    }

    float mx = score[0];
#pragma unroll
    for (int j = 1; j < NIM; j++) mx = fmaxf(mx, score[j]);
    float sum = 0.f;
#pragma unroll
    for (int j = 0; j < NIM; j++) { score[j] = expf(score[j] - mx); sum += score[j]; }
    const float inv = 1.f / sum;

    float4 o = make_float4(0.f, 0.f, 0.f, 0.f);
#pragma unroll
    for (int j = 0; j < NIM; j++) {
        float w = score[j] * inv;
        o.x = fmaf(w, vkeep[j].x, o.x);
        o.y = fmaf(w, vkeep[j].y, o.y);
        o.z = fmaf(w, vkeep[j].z, o.z);
        o.w = fmaf(w, vkeep[j].w, o.w);
    }
    o_s[wp][lane * 4 + 0] = o.x;
    o_s[wp][lane * 4 + 1] = o.y;
    o_s[wp][lane * 4 + 2] = o.z;
    o_s[wp][lane * 4 + 3] = o.w;
    __syncthreads();

    // transposed coalesced-ish store: oT[c][b*NTRI + n0 + 0..7]
    const int c = threadIdx.x >> 1, h = threadIdx.x & 1;
    float4 v;
    v.x = o_s[h * 4 + 0][c];
    v.y = o_s[h * 4 + 1][c];
    v.z = o_s[h * 4 + 2][c];
    v.w = o_s[h * 4 + 3][c];
    *(float4*)(g_oT + (size_t)c * NROWS + (size_t)b * NTRI + blockIdx.x * 8 + h * 4) = v;
}

// ------------------- launch -------------------------------------------------
extern "C" void kernel_launch(void* const* d_in, const int* in_sizes, int n_in,
                              void* d_out, int out_size)
{
    const float* tf     = (const float*)d_in[0];
    const float* img    = (const float*)d_in[1];
    const float* proj   = (const float*)d_in[2];
    const float* k_w    = (const float*)d_in[4];
    const float* k_b    = (const float*)d_in[5];
    const float* q_w    = (const float*)d_in[6];
    const float* q_b    = (const float*)d_in[7];
    const float* v_w    = (const float*)d_in[8];
    const float* v_b    = (const float*)d_in[9];
    const float* in_w   = (const float*)d_in[10];
    const float* in_b   = (const float*)d_in[11];
    const float* out_w  = (const float*)d_in[12];
    const float* out_b  = (const float*)d_in[13];
    const float* conv_w = (const float*)d_in[14];
    const float* conv_b = (const float*)d_in[15];
    float* out = (float*)d_out;

    float *p_WkT, *p_WvT, *p_WcT, *p_WcatT, *p_WocT, *p_bKV, *p_boc;
    float *p_pe_triT, *p_imgT, *p_vol, *p_qp, *p_oT;
    cudaGetSymbolAddress((void**)&p_WkT, g_WkT);
    cudaGetSymbolAddress((void**)&p_WvT, g_WvT);
    cudaGetSymbolAddress((void**)&p_WcT, g_WcT);
    cudaGetSymbolAddress((void**)&p_WcatT, g_WcatT);
    cudaGetSymbolAddress((void**)&p_WocT, g_WocT);
    cudaGetSymbolAddress((void**)&p_bKV, g_bKV);
    cudaGetSymbolAddress((void**)&p_boc, g_boc);
    cudaGetSymbolAddress((void**)&p_pe_triT, g_pe_triT);
    cudaGetSymbolAddress((void**)&p_imgT, g_imgT);
    cudaGetSymbolAddress((void**)&p_vol, g_vol);
    cudaGetSymbolAddress((void**)&p_qp,  g_qp);
    cudaGetSymbolAddress((void**)&p_oT,  g_oT);

    const long long BIG = 1LL << 60;

    // L1: PE tables (+folded biases)
    pe_fill_kernel<<<(256 * 128 + 128 * NTRI) / 256, 256>>>(q_b, k_b, v_b);
    // L2: transposes (WkT, WvT, imgT)
    transpose_all_kernel<<<32 + 20 * 320, 256>>>(in_w, img);
    // L3: small precomputes (bKV, WcatT, WocT, boc)
    small_all_kernel<<<385, 256>>>(in_w, in_b, q_w, out_w, out_b, conv_w, conv_b);

    // L4: WcT = [ (k_w^T Wk^T) | (v_w^T Wv^T) ]  -> [e][c], dual cfg 40+40 CTAs
    {
        GCfg ck = { k_w, BIG, 0, IMGC,  nullptr, 0, 1, 1 << 30,
                    p_WkT, 128, nullptr, nullptr, 1, 1,
                    p_WcT, 256, 128, 2, 0 };
        GCfg cv = { v_w, BIG, 0, IMGC,  nullptr, 0, 1, 1 << 30,
                    p_WvT, 128, nullptr, nullptr, 1, 1,
                    p_WcT + 128, 256, 128, 2, 0 };
        gemm_f2_kernel<false><<<80, 128>>>(ck, cv, 40);
    }

    // L5: mega GEMM: volKV (320 CTAs) + qp (1536 CTAs)
    {
        GCfg cvol = { p_imgT, 256, 1280LL * 256, 256,  nullptr, 0, 1, 1 << 30,
                      p_WcT, 256, nullptr, p_bKV, 256, 256,
                      p_vol, 256, IMGC, 4, 0 };
        GCfg cqp  = { tf, NTRI, 64LL * NTRI, NTRI,  p_pe_triT, NTRI, NTRI, 64,
                      p_WcatT, 128, in_b, nullptr, 1, 1,
                      p_qp, 128, 192, 2, 0 };
        gemm_f2_kernel<false><<<320 + 1536, 128>>>(cvol, cqp, 320);
    }

    // L6: fused sample + attention -> oT
    fused_attn_kernel<<<dim3(NTRI / 8, NB), 256>>>(proj);

    // L7: out[b][oc][n] = oT^T @ WocT + boc (transposed, smem-staged store)
    {
        GCfg cf = { p_oT, BIG, 0, NROWS,  nullptr, 0, 1, 1 << 30,
                    p_WocT, 64, p_boc, nullptr, 1, 1,
                    out, 64, 128, 1, NTRI };
        gemm_f2_kernel<true><<<768, 128>>>(cf, cf, 768);
    }
}